// round 6
// baseline (speedup 1.0000x reference)
#include <cuda_runtime.h>
#include <cuda_bf16.h>
#include <math.h>
#include <stdint.h>

#define BB   4
#define NSEQ 2048
#define EMB  1024
#define NH   16
#define HD   64
#define NTOK (BB * NSEQ)      // 8192
#define QKVN (3 * EMB)        // 3072

typedef __nv_bfloat16 bf16;

// ---------------- scratch (__device__ globals; allocation-free) -------------
__device__ bf16 g_xh[NTOK * EMB],  g_xl[NTOK * EMB];
__device__ bf16 g_wqh[QKVN * EMB], g_wql[QKVN * EMB];
__device__ bf16 g_wph[EMB * EMB],  g_wpl[EMB * EMB];
__device__ bf16 g_qh[BB*NH*NSEQ*HD], g_ql[BB*NH*NSEQ*HD];
__device__ bf16 g_kh[BB*NH*NSEQ*HD], g_kl[BB*NH*NSEQ*HD];
__device__ bf16 g_vh[BB*NH*NSEQ*HD], g_vl[BB*NH*NSEQ*HD];
__device__ bf16 g_atth[NTOK * EMB], g_attl[NTOK * EMB];

// ---------------- helpers ----------------------------------------------------
__device__ __forceinline__ uint32_t smaddr(const void* p) {
    return (uint32_t)__cvta_generic_to_shared(p);
}
__device__ __forceinline__ void ldsm_x4(uint32_t& r0, uint32_t& r1, uint32_t& r2,
                                        uint32_t& r3, uint32_t a) {
    asm volatile("ldmatrix.sync.aligned.m8n8.x4.shared.b16 {%0,%1,%2,%3},[%4];\n"
                 : "=r"(r0), "=r"(r1), "=r"(r2), "=r"(r3) : "r"(a));
}
__device__ __forceinline__ void ldsm_x4t(uint32_t& r0, uint32_t& r1, uint32_t& r2,
                                         uint32_t& r3, uint32_t a) {
    asm volatile("ldmatrix.sync.aligned.m8n8.x4.trans.shared.b16 {%0,%1,%2,%3},[%4];\n"
                 : "=r"(r0), "=r"(r1), "=r"(r2), "=r"(r3) : "r"(a));
}
__device__ __forceinline__ void mma_bf16(float c[4], const uint32_t a[4],
                                         const uint32_t b[2]) {
    asm volatile(
        "mma.sync.aligned.m16n8k16.row.col.f32.bf16.bf16.f32 "
        "{%0,%1,%2,%3}, {%4,%5,%6,%7}, {%8,%9}, {%0,%1,%2,%3};\n"
        : "+f"(c[0]), "+f"(c[1]), "+f"(c[2]), "+f"(c[3])
        : "r"(a[0]), "r"(a[1]), "r"(a[2]), "r"(a[3]), "r"(b[0]), "r"(b[1]));
}
__device__ __forceinline__ void bsplit(float v, bf16& h, bf16& l) {
    h = __float2bfloat16(v);
    l = __float2bfloat16(v - __bfloat162float(h));
}
__device__ __forceinline__ uint32_t pack2(bf16 a, bf16 b) {
    __nv_bfloat162 t; t.x = a; t.y = b;
    return *(uint32_t*)&t;
}
// FMA-pipe exp (no MUFU). Valid for x <= 0 (clamped below).
__device__ __forceinline__ float fast_exp(float x) {
    x = fmaxf(x, -86.0f);
    float y = x * 1.4426950408889634f;
    float r = rintf(y);
    float f = y - r;
    float p = 0.00133819f;
    p = fmaf(p, f, 0.00961804f);
    p = fmaf(p, f, 0.05550411f);
    p = fmaf(p, f, 0.24022651f);
    p = fmaf(p, f, 0.69314718f);
    p = fmaf(p, f, 1.0f);
    int e = (int)r;
    return p * __int_as_float((e + 127) << 23);
}
__device__ __forceinline__ void cp16(void* dst, const void* src) {
    asm volatile("cp.async.cg.shared.global [%0],[%1],16;\n"
                 :: "r"(smaddr(dst)), "l"(src));
}
__device__ __forceinline__ void cpcommit() {
    asm volatile("cp.async.commit_group;\n");
}
template <int N>
__device__ __forceinline__ void cpwait() {
    asm volatile("cp.async.wait_group %0;\n" :: "n"(N));
}
__device__ __forceinline__ uint32_t sw64(uint32_t off) {
    return off ^ ((off >> 3) & 0x30);
}

// ---------------- split kernel (fp32 -> bf16 hi/lo) --------------------------
__global__ void __launch_bounds__(256) split_kernel(
    const float4* __restrict__ in, __nv_bfloat162* __restrict__ h,
    __nv_bfloat162* __restrict__ l, int n4)
{
    int i = blockIdx.x * 256 + threadIdx.x;
    if (i >= n4) return;
    float4 v = in[i];
    bf16 h0, l0, h1, l1, h2, l2, h3, l3;
    bsplit(v.x, h0, l0); bsplit(v.y, h1, l1);
    bsplit(v.z, h2, l2); bsplit(v.w, h3, l3);
    __nv_bfloat162 t;
    t.x = h0; t.y = h1; h[2 * i] = t;
    t.x = h2; t.y = h3; h[2 * i + 1] = t;
    t.x = l0; t.y = l1; l[2 * i] = t;
    t.x = l2; t.y = l3; l[2 * i + 1] = t;
}

// ---------------- GEMM (NT, bf16 3-pass split, mma.sync) ---------------------
// 128x128 tile, K-chunks of 32, 3-stage cp.async, 2 CTAs/SM (96 KB smem).
#define KCH      32
#define NKT      (EMB / KCH)          // 32
#define GT_B     (128 * 64)           // 8 KB per array per stage
#define G_STAGES 3
#define GEMM_SMEM (G_STAGES * 4 * GT_B)  // 98304

template <int MODE>
__global__ void __launch_bounds__(256, 2) gemm_bf16(
    const bf16* __restrict__ Ah_, const bf16* __restrict__ Al_,
    const bf16* __restrict__ Wh_, const bf16* __restrict__ Wl_,
    const float* __restrict__ bias, float* __restrict__ Cout)
{
    constexpr int K = EMB;
    extern __shared__ char smg[];

    const int tid  = threadIdx.x;
    const int lane = tid & 31;
    const int warp = tid >> 5;
    const int m0 = blockIdx.y * 128;
    const int n0 = blockIdx.x * 128;
    const int wm = (warp >> 1) * 32;
    const int wn = (warp & 1) * 64;

    const int a_row = lane & 15;
    const int a_csel = (lane >> 4) * 8;
    const int b_nrow = (lane & 7) + (lane >> 4) * 8;
    const int b_kcol = ((lane >> 3) & 1) * 8;

    float acc[2][8][4];
#pragma unroll
    for (int i = 0; i < 2; i++)
#pragma unroll
        for (int j = 0; j < 8; j++)
#pragma unroll
            for (int e = 0; e < 4; e++) acc[i][j][e] = 0.f;

    auto tile = [&](int st, int arr) -> char* { return smg + (st * 4 + arr) * GT_B; };

    auto load_chunk = [&](int st, int kt) {
        const int k0 = kt * KCH;
#pragma unroll
        for (int arr = 0; arr < 4; arr++) {
            const bf16* base =
                (arr == 0) ? Ah_ + (size_t)m0 * K :
                (arr == 1) ? Al_ + (size_t)m0 * K :
                (arr == 2) ? Wh_ + (size_t)n0 * K : Wl_ + (size_t)n0 * K;
            char* dst = tile(st, arr);
#pragma unroll
            for (int i = 0; i < 2; i++) {
                int idx = tid + i * 256;
                int r  = idx >> 2;
                int c4 = idx & 3;
                uint32_t off = sw64((uint32_t)(r * 64 + c4 * 16));
                cp16(dst + off, base + (size_t)r * K + k0 + c4 * 8);
            }
        }
    };

    load_chunk(0, 0); cpcommit();
    load_chunk(1, 1); cpcommit();

    for (int kt = 0; kt < NKT; kt++) {
        const int st = kt % 3;
        if (kt == NKT - 1) cpwait<0>(); else cpwait<1>();
        __syncthreads();

        char* sAh = tile(st, 0);
        char* sAl = tile(st, 1);
        char* sWh = tile(st, 2);
        char* sWl = tile(st, 3);
#pragma unroll
        for (int kc = 0; kc < 2; kc++) {
            const uint32_t acol = (uint32_t)((kc * 16 + a_csel) * 2);
            const uint32_t bcol = (uint32_t)((kc * 16 + b_kcol) * 2);
            uint32_t ah[2][4], al[2][4];
#pragma unroll
            for (int i = 0; i < 2; i++) {
                uint32_t off = sw64((uint32_t)((wm + i * 16 + a_row) * 64) + acol);
                ldsm_x4(ah[i][0], ah[i][1], ah[i][2], ah[i][3], smaddr(sAh + off));
                ldsm_x4(al[i][0], al[i][1], al[i][2], al[i][3], smaddr(sAl + off));
            }
            uint32_t bh[8][2], bl[8][2];
#pragma unroll
            for (int jp = 0; jp < 4; jp++) {
                uint32_t off = sw64((uint32_t)((wn + jp * 16 + b_nrow) * 64) + bcol);
                ldsm_x4(bh[2 * jp][0], bh[2 * jp][1], bh[2 * jp + 1][0], bh[2 * jp + 1][1],
                        smaddr(sWh + off));
                ldsm_x4(bl[2 * jp][0], bl[2 * jp][1], bl[2 * jp + 1][0], bl[2 * jp + 1][1],
                        smaddr(sWl + off));
            }
#pragma unroll
            for (int i = 0; i < 2; i++)
#pragma unroll
                for (int j = 0; j < 8; j++) {
                    mma_bf16(acc[i][j], ah[i], bh[j]);
                    mma_bf16(acc[i][j], ah[i], bl[j]);
                    mma_bf16(acc[i][j], al[i], bh[j]);
                }
        }

        if (kt + 2 < NKT) {
            load_chunk((kt + 2) % 3, kt + 2);
            cpcommit();
        }
    }

    const int g = lane >> 2, t = lane & 3;
    if (MODE == 0) {
#pragma unroll
        for (int i = 0; i < 2; i++)
#pragma unroll
            for (int j = 0; j < 8; j++)
#pragma unroll
                for (int e = 0; e < 4; e++) {
                    int row = m0 + wm + i * 16 + g + (e >> 1) * 8;
                    int col = n0 + wn + j * 8 + 2 * t + (e & 1);
                    float val = acc[i][j][e] + bias[col];
                    int h = col / 192;
                    int rem = col - h * 192;
                    int d = rem / 3;
                    int which = rem - d * 3;
                    int bb = row >> 11;
                    int nn = row & (NSEQ - 1);
                    size_t idx = ((size_t)(bb * NH + h) * NSEQ + nn) * HD + d;
                    bf16 hi, lo;
                    if (which == 0) {
                        bsplit(val * 0.125f, hi, lo);
                        g_qh[idx] = hi; g_ql[idx] = lo;
                    } else if (which == 1) {
                        bsplit(val, hi, lo);
                        g_kh[idx] = hi; g_kl[idx] = lo;
                    } else {
                        bsplit(val, hi, lo);
                        g_vh[idx] = hi; g_vl[idx] = lo;
                    }
                }
    } else {
#pragma unroll
        for (int i = 0; i < 2; i++)
#pragma unroll
            for (int j = 0; j < 8; j++)
#pragma unroll
                for (int e = 0; e < 4; e++) {
                    int row = m0 + wm + i * 16 + g + (e >> 1) * 8;
                    int col = n0 + wn + j * 8 + 2 * t + (e & 1);
                    Cout[(size_t)row * EMB + col] = acc[i][j][e] + bias[col];
                }
    }
}

// ---------------- flash attention --------------------------------------------
// 64 q-rows / 4 warps / 128 threads per CTA -> 2 CTAs/SM.
// Single-buffered Kh/Kl/Vh/Vl with split-phase cp.async prefetch:
//   K(t+1) loads overlap softmax+PV(t); V(t+1) loads overlap S(t+1).
#define ATQ 64
#define NKV (NSEQ / 128)                 // 16 KV tiles
#define AQ_TILE (ATQ * 72)               // Q tile elems
#define AK_TILE (128 * 72)               // KV tile elems
#define ATTN_SMEM ((2 * AQ_TILE + 4 * AK_TILE) * 2)   // 92160 bytes

__global__ void __launch_bounds__(128, 2) attn_bf16()
{
    extern __shared__ bf16 sm[];
    bf16* Qh = sm;
    bf16* Ql = sm + AQ_TILE;
    bf16* Kh = sm + 2 * AQ_TILE;
    bf16* Kl = Kh + AK_TILE;
    bf16* Vh = Kl + AK_TILE;
    bf16* Vl = Vh + AK_TILE;

    const int tid  = threadIdx.x;
    const int lane = tid & 31;
    const int warp = tid >> 5;            // 0..3
    const int bh = blockIdx.y;
    const int b  = bh >> 4;
    const int h  = bh & 15;
    const int q0 = blockIdx.x * ATQ;

    const bf16* Qgh = g_qh + (size_t)bh * NSEQ * HD;
    const bf16* Qgl = g_ql + (size_t)bh * NSEQ * HD;
    const bf16* Kgh = g_kh + (size_t)bh * NSEQ * HD;
    const bf16* Kgl = g_kl + (size_t)bh * NSEQ * HD;
    const bf16* Vgh = g_vh + (size_t)bh * NSEQ * HD;
    const bf16* Vgl = g_vl + (size_t)bh * NSEQ * HD;

    const int a_row = lane & 15;
    const int a_csel = (lane >> 4) * 8;
    const int b_nrow = (lane & 7) + (lane >> 4) * 8;
    const int b_kcol = ((lane >> 3) & 1) * 8;
    const int g = lane >> 2, t = lane & 3;

    auto load_k = [&](int t0) {
#pragma unroll
        for (int i = 0; i < 8; i++) {
            int s = tid + i * 128;
            int r = s >> 3;
            int c = (s & 7) * 8;
            cp16(Kh + r * 72 + c, Kgh + (size_t)(t0 + r) * HD + c);
            cp16(Kl + r * 72 + c, Kgl + (size_t)(t0 + r) * HD + c);
        }
    };
    auto load_v = [&](int t0) {
#pragma unroll
        for (int i = 0; i < 8; i++) {
            int s = tid + i * 128;
            int r = s >> 3;
            int c = (s & 7) * 8;
            cp16(Vh + r * 72 + c, Vgh + (size_t)(t0 + r) * HD + c);
            cp16(Vl + r * 72 + c, Vgl + (size_t)(t0 + r) * HD + c);
        }
    };

    // prologue: Q + K(0) in group A0; V(0) in group B0
#pragma unroll
    for (int i = 0; i < 4; i++) {
        int s = tid + i * 128;
        int r = s >> 3;
        int c = (s & 7) * 8;
        cp16(Qh + r * 72 + c, Qgh + (size_t)(q0 + r) * HD + c);
        cp16(Ql + r * 72 + c, Qgl + (size_t)(q0 + r) * HD + c);
    }
    load_k(0);
    cpcommit();          // A0
    load_v(0);
    cpcommit();          // B0

    cpwait<1>();         // A0 done (Q + K0)
    __syncthreads();

    // Q fragments into registers, held for whole loop
    uint32_t qh[4][4], ql[4][4];
#pragma unroll
    for (int kc = 0; kc < 4; kc++) {
        uint32_t ad = smaddr(&Qh[(16 * warp + a_row) * 72 + kc * 16 + a_csel]);
        ldsm_x4(qh[kc][0], qh[kc][1], qh[kc][2], qh[kc][3], ad);
        ad = smaddr(&Ql[(16 * warp + a_row) * 72 + kc * 16 + a_csel]);
        ldsm_x4(ql[kc][0], ql[kc][1], ql[kc][2], ql[kc][3], ad);
    }

    float oacc[8][4];
#pragma unroll
    for (int j = 0; j < 8; j++)
#pragma unroll
        for (int e = 0; e < 4; e++) oacc[j][e] = 0.f;
    float m0r = -1e30f, m1r = -1e30f, l0 = 0.f, l1 = 0.f;

    for (int ti = 0; ti < NKV; ti++) {
        // K(ti) ready: pending groups <= {B_ti} or {B_ti, A_(ti+1)} handled below
        if (ti > 0) {
            cpwait<1>();             // A_ti (K tile) complete
            __syncthreads();
        }

        // ---- S = Q K^T (3-pass split) ----
        float sacc[16][4];
#pragma unroll
        for (int j = 0; j < 16; j++)
#pragma unroll
            for (int e = 0; e < 4; e++) sacc[j][e] = 0.f;

#pragma unroll
        for (int kc = 0; kc < 4; kc++) {
#pragma unroll
            for (int jp = 0; jp < 8; jp++) {
                uint32_t bh4[4], bl4[4];
                uint32_t ad = smaddr(&Kh[(jp * 16 + b_nrow) * 72 + kc * 16 + b_kcol]);
                ldsm_x4(bh4[0], bh4[1], bh4[2], bh4[3], ad);
                ad = smaddr(&Kl[(jp * 16 + b_nrow) * 72 + kc * 16 + b_kcol]);
                ldsm_x4(bl4[0], bl4[1], bl4[2], bl4[3], ad);
                mma_bf16(sacc[2 * jp],     qh[kc], &bh4[0]);
                mma_bf16(sacc[2 * jp],     qh[kc], &bl4[0]);
                mma_bf16(sacc[2 * jp],     ql[kc], &bh4[0]);
                mma_bf16(sacc[2 * jp + 1], qh[kc], &bh4[2]);
                mma_bf16(sacc[2 * jp + 1], qh[kc], &bl4[2]);
                mma_bf16(sacc[2 * jp + 1], ql[kc], &bh4[2]);
            }
        }
        __syncthreads();             // all warps done reading K buffer
        if (ti + 1 < NKV) {
            load_k((ti + 1) * 128);  // overlaps softmax + PV
            cpcommit();              // A_(ti+1)
        }

        // ---- register softmax ----
        float mx0 = -1e30f, mx1 = -1e30f;
#pragma unroll
        for (int j = 0; j < 16; j++) {
            mx0 = fmaxf(mx0, fmaxf(sacc[j][0], sacc[j][1]));
            mx1 = fmaxf(mx1, fmaxf(sacc[j][2], sacc[j][3]));
        }
        mx0 = fmaxf(mx0, __shfl_xor_sync(0xffffffffu, mx0, 1));
        mx0 = fmaxf(mx0, __shfl_xor_sync(0xffffffffu, mx0, 2));
        mx1 = fmaxf(mx1, __shfl_xor_sync(0xffffffffu, mx1, 1));
        mx1 = fmaxf(mx1, __shfl_xor_sync(0xffffffffu, mx1, 2));
        float mn0 = fmaxf(m0r, mx0), mn1 = fmaxf(m1r, mx1);
        float al0 = fast_exp(m0r - mn0), al1 = fast_exp(m1r - mn1);
        m0r = mn0; m1r = mn1;

        float s0 = 0.f, s1 = 0.f;
        uint32_t aph[8][4], apl[8][4];
#pragma unroll
        for (int j2 = 0; j2 < 8; j2++) {
            float p[8];
            p[0] = fast_exp(sacc[2 * j2][0] - mn0);
            p[1] = fast_exp(sacc[2 * j2][1] - mn0);
            p[2] = fast_exp(sacc[2 * j2][2] - mn1);
            p[3] = fast_exp(sacc[2 * j2][3] - mn1);
            p[4] = fast_exp(sacc[2 * j2 + 1][0] - mn0);
            p[5] = fast_exp(sacc[2 * j2 + 1][1] - mn0);
            p[6] = fast_exp(sacc[2 * j2 + 1][2] - mn1);
            p[7] = fast_exp(sacc[2 * j2 + 1][3] - mn1);
            s0 += p[0] + p[1] + p[4] + p[5];
            s1 += p[2] + p[3] + p[6] + p[7];
            bf16 hb[8]; float lf[8];
#pragma unroll
            for (int e = 0; e < 8; e++) {
                hb[e] = __float2bfloat16(p[e]);
                lf[e] = p[e] - __bfloat162float(hb[e]);
            }
            aph[j2][0] = pack2(hb[0], hb[1]);
            aph[j2][1] = pack2(hb[2], hb[3]);
            aph[j2][2] = pack2(hb[4], hb[5]);
            aph[j2][3] = pack2(hb[6], hb[7]);
            apl[j2][0] = pack2(__float2bfloat16(lf[0]), __float2bfloat16(lf[1]));
            apl[j2][1] = pack2(__float2bfloat16(lf[2]), __float2bfloat16(lf[3]));
            apl[j2][2] = pack2(__float2bfloat16(lf[4]), __float2bfloat16(lf[5]));
            apl[j2][3] = pack2(__float2bfloat16(lf[6]), __float2bfloat16(lf[7]));
        }
        s0 += __shfl_xor_sync(0xffffffffu, s0, 1);
        s0 += __shfl_xor_sync(0xffffffffu, s0, 2);
        s1 += __shfl_xor_sync(0xffffffffu, s1, 1);
        s1 += __shfl_xor_sync(0xffffffffu, s1, 2);
        l0 = l0 * al0 + s0;
        l1 = l1 * al1 + s1;

#pragma unroll
        for (int j = 0; j < 8; j++) {
            oacc[j][0] *= al0; oacc[j][1] *= al0;
            oacc[j][2] *= al1; oacc[j][3] *= al1;
        }

        // ---- wait V(ti), then O += P V ----
        if (ti + 1 < NKV) cpwait<1>(); else cpwait<0>();
        __syncthreads();

#pragma unroll
        for (int kc = 0; kc < 8; kc++) {
#pragma unroll
            for (int jp = 0; jp < 4; jp++) {
                uint32_t bh4[4], bl4[4];
                uint32_t ad = smaddr(&Vh[(kc * 16 + a_row) * 72 + jp * 16 + a_csel]);
                ldsm_x4t(bh4[0], bh4[1], bh4[2], bh4[3], ad);
                ad = smaddr(&Vl[(kc * 16 + a_row) * 72 + jp * 16 + a_csel]);
                ldsm_x4t(bl4[0], bl4[1], bl4[2], bl4[3], ad);
                mma_bf16(oacc[2 * jp],     aph[kc], &bh4[0]);
                mma_bf16(oacc[2 * jp],     aph[kc], &bl4[0]);
                mma_bf16(oacc[2 * jp],     apl[kc], &bh4[0]);
                mma_bf16(oacc[2 * jp + 1], aph[kc], &bh4[2]);
                mma_bf16(oacc[2 * jp + 1], aph[kc], &bl4[2]);
                mma_bf16(oacc[2 * jp + 1], apl[kc], &bh4[2]);
            }
        }
        __syncthreads();             // all warps done reading V buffer
        if (ti + 1 < NKV) {
            load_v((ti + 1) * 128);  // overlaps next S
            cpcommit();              // B_(ti+1)
        }
    }

    // ---- epilogue ----
    float inv0 = 1.0f / l0;
    float inv1 = 1.0f / l1;
#pragma unroll
    for (int j = 0; j < 8; j++)
#pragma unroll
        for (int e = 0; e < 4; e++) {
            int row = 16 * warp + g + (e >> 1) * 8;
            int col = j * 8 + 2 * t + (e & 1);
            float val = oacc[j][e] * ((e >> 1) ? inv1 : inv0);
            size_t off = ((size_t)b * NSEQ + q0 + row) * EMB + h * HD + col;
            bf16 hi, lo;
            bsplit(val, hi, lo);
            g_atth[off] = hi;
            g_attl[off] = lo;
        }
}

// ---------------------------------------------------------------------------
extern "C" void kernel_launch(void* const* d_in, const int* in_sizes, int n_in,
                              void* d_out, int out_size)
{
    const float* x      = (const float*)d_in[0];
    const float* w_qkv  = (const float*)d_in[1];
    const float* b_qkv  = (const float*)d_in[2];
    const float* w_proj = (const float*)d_in[3];
    const float* b_proj = (const float*)d_in[4];
    float* out = (float*)d_out;

    cudaFuncSetAttribute(gemm_bf16<0>, cudaFuncAttributeMaxDynamicSharedMemorySize, GEMM_SMEM);
    cudaFuncSetAttribute(gemm_bf16<1>, cudaFuncAttributeMaxDynamicSharedMemorySize, GEMM_SMEM);
    cudaFuncSetAttribute(attn_bf16, cudaFuncAttributeMaxDynamicSharedMemorySize, (int)ATTN_SMEM);

    bf16 *xh, *xl, *wqh, *wql, *wph, *wpl, *atth, *attl;
    cudaGetSymbolAddress((void**)&xh,  g_xh);  cudaGetSymbolAddress((void**)&xl,  g_xl);
    cudaGetSymbolAddress((void**)&wqh, g_wqh); cudaGetSymbolAddress((void**)&wql, g_wql);
    cudaGetSymbolAddress((void**)&wph, g_wph); cudaGetSymbolAddress((void**)&wpl, g_wpl);
    cudaGetSymbolAddress((void**)&atth, g_atth); cudaGetSymbolAddress((void**)&attl, g_attl);

    // 1) split inputs to bf16 hi/lo
    split_kernel<<<(NTOK * EMB) / 1024, 256>>>((const float4*)x,
        (__nv_bfloat162*)xh, (__nv_bfloat162*)xl, NTOK * EMB / 4);
    split_kernel<<<(QKVN * EMB) / 1024, 256>>>((const float4*)w_qkv,
        (__nv_bfloat162*)wqh, (__nv_bfloat162*)wql, QKVN * EMB / 4);
    split_kernel<<<(EMB * EMB) / 1024, 256>>>((const float4*)w_proj,
        (__nv_bfloat162*)wph, (__nv_bfloat162*)wpl, EMB * EMB / 4);

    // 2) QKV projection + scatter (q pre-scaled by 1/8, split to bf16 hi/lo)
    gemm_bf16<0><<<dim3(QKVN / 128, NTOK / 128), 256, GEMM_SMEM>>>(
        xh, xl, wqh, wql, b_qkv, nullptr);

    // 3) flash attention (64-row q tiles, 2 CTAs/SM)
    attn_bf16<<<dim3(NSEQ / ATQ, BB * NH), 128, ATTN_SMEM>>>();

    // 4) output projection
    gemm_bf16<1><<<dim3(EMB / 128, NTOK / 128), 256, GEMM_SMEM>>>(
        atth, attl, wph, wpl, b_proj, out);
}

// round 7
// speedup vs baseline: 2.2412x; 2.2412x over previous
#include <cuda_runtime.h>
#include <cuda_fp16.h>
#include <math.h>
#include <stdint.h>

#define BB   4
#define NSEQ 2048
#define EMB  1024
#define NH   16
#define HD   64
#define NTOK (BB * NSEQ)      // 8192
#define QKVN (3 * EMB)        // 3072

typedef __half f16;

// ---------------- scratch (__device__ globals; allocation-free) -------------
__device__ f16 g_xh[NTOK * EMB],  g_xl[NTOK * EMB];
__device__ f16 g_wqh[QKVN * EMB];
__device__ f16 g_wph[EMB * EMB];
__device__ f16 g_qh[BB*NH*NSEQ*HD], g_ql[BB*NH*NSEQ*HD];
__device__ f16 g_kh[BB*NH*NSEQ*HD];
__device__ f16 g_vh[BB*NH*NSEQ*HD];
__device__ f16 g_atth[NTOK * EMB], g_attl[NTOK * EMB];

// ---------------- helpers ----------------------------------------------------
__device__ __forceinline__ uint32_t smaddr(const void* p) {
    return (uint32_t)__cvta_generic_to_shared(p);
}
__device__ __forceinline__ void ldsm_x4(uint32_t& r0, uint32_t& r1, uint32_t& r2,
                                        uint32_t& r3, uint32_t a) {
    asm volatile("ldmatrix.sync.aligned.m8n8.x4.shared.b16 {%0,%1,%2,%3},[%4];\n"
                 : "=r"(r0), "=r"(r1), "=r"(r2), "=r"(r3) : "r"(a));
}
__device__ __forceinline__ void ldsm_x4t(uint32_t& r0, uint32_t& r1, uint32_t& r2,
                                         uint32_t& r3, uint32_t a) {
    asm volatile("ldmatrix.sync.aligned.m8n8.x4.trans.shared.b16 {%0,%1,%2,%3},[%4];\n"
                 : "=r"(r0), "=r"(r1), "=r"(r2), "=r"(r3) : "r"(a));
}
__device__ __forceinline__ void mma_f16(float c[4], const uint32_t a[4],
                                        const uint32_t b[2]) {
    asm volatile(
        "mma.sync.aligned.m16n8k16.row.col.f32.f16.f16.f32 "
        "{%0,%1,%2,%3}, {%4,%5,%6,%7}, {%8,%9}, {%0,%1,%2,%3};\n"
        : "+f"(c[0]), "+f"(c[1]), "+f"(c[2]), "+f"(c[3])
        : "r"(a[0]), "r"(a[1]), "r"(a[2]), "r"(a[3]), "r"(b[0]), "r"(b[1]));
}
__device__ __forceinline__ void hsplit(float v, f16& h, f16& l) {
    h = __float2half_rn(v);
    l = __float2half_rn(v - __half2float(h));
}
__device__ __forceinline__ uint32_t pack2h(f16 a, f16 b) {
    __half2 t; t.x = a; t.y = b;
    return *(uint32_t*)&t;
}
// FMA-pipe exp (no MUFU). Valid for x <= 0 (clamped below).
__device__ __forceinline__ float fast_exp(float x) {
    x = fmaxf(x, -86.0f);
    float y = x * 1.4426950408889634f;
    float r = rintf(y);
    float f = y - r;
    float p = 0.00133819f;
    p = fmaf(p, f, 0.00961804f);
    p = fmaf(p, f, 0.05550411f);
    p = fmaf(p, f, 0.24022651f);
    p = fmaf(p, f, 0.69314718f);
    p = fmaf(p, f, 1.0f);
    int e = (int)r;
    return p * __int_as_float((e + 127) << 23);
}
__device__ __forceinline__ void cp16(void* dst, const void* src) {
    asm volatile("cp.async.cg.shared.global [%0],[%1],16;\n"
                 :: "r"(smaddr(dst)), "l"(src));
}
__device__ __forceinline__ void cpcommit() {
    asm volatile("cp.async.commit_group;\n");
}
template <int N>
__device__ __forceinline__ void cpwait() {
    asm volatile("cp.async.wait_group %0;\n" :: "n"(N));
}
__device__ __forceinline__ uint32_t sw64(uint32_t off) {
    return off ^ ((off >> 3) & 0x30);
}

// ---------------- split kernels (fp32 -> fp16 hi/lo or hi only) --------------
__global__ void __launch_bounds__(256) split2_kernel(
    const float4* __restrict__ in, __half2* __restrict__ h,
    __half2* __restrict__ l, int n4)
{
    int i = blockIdx.x * 256 + threadIdx.x;
    if (i >= n4) return;
    float4 v = in[i];
    f16 h0, l0, h1, l1, h2, l2, h3, l3;
    hsplit(v.x, h0, l0); hsplit(v.y, h1, l1);
    hsplit(v.z, h2, l2); hsplit(v.w, h3, l3);
    __half2 t;
    t.x = h0; t.y = h1; h[2 * i] = t;
    t.x = h2; t.y = h3; h[2 * i + 1] = t;
    t.x = l0; t.y = l1; l[2 * i] = t;
    t.x = l2; t.y = l3; l[2 * i + 1] = t;
}
__global__ void __launch_bounds__(256) round1_kernel(
    const float4* __restrict__ in, __half2* __restrict__ h, int n4)
{
    int i = blockIdx.x * 256 + threadIdx.x;
    if (i >= n4) return;
    float4 v = in[i];
    __half2 t;
    t.x = __float2half_rn(v.x); t.y = __float2half_rn(v.y); h[2 * i] = t;
    t.x = __float2half_rn(v.z); t.y = __float2half_rn(v.w); h[2 * i + 1] = t;
}

// ---------------- GEMM (NT, fp16 2-pass split, mma.sync) ---------------------
// C = (Ah+Al) * Wh^T. 128x128 tile, K-chunks of 32, 3-stage cp.async.
// Arrays per stage: Ah, Al, Wh (3 x 8KB) -> 72 KB smem, 2 CTAs/SM.
#define KCH      32
#define NKT      (EMB / KCH)          // 32
#define GT_B     (128 * 64)           // 8 KB per array per stage
#define G_STAGES 3
#define GEMM_SMEM (G_STAGES * 3 * GT_B)  // 73728

template <int MODE>
__global__ void __launch_bounds__(256, 2) gemm_f16(
    const f16* __restrict__ Ah_, const f16* __restrict__ Al_,
    const f16* __restrict__ Wh_,
    const float* __restrict__ bias, float* __restrict__ Cout)
{
    constexpr int K = EMB;
    extern __shared__ char smg[];

    const int tid  = threadIdx.x;
    const int lane = tid & 31;
    const int warp = tid >> 5;
    const int m0 = blockIdx.y * 128;
    const int n0 = blockIdx.x * 128;
    const int wm = (warp >> 1) * 32;
    const int wn = (warp & 1) * 64;

    const int a_row = lane & 15;
    const int a_csel = (lane >> 4) * 8;
    const int b_nrow = (lane & 7) + (lane >> 4) * 8;
    const int b_kcol = ((lane >> 3) & 1) * 8;

    float acc[2][8][4];
#pragma unroll
    for (int i = 0; i < 2; i++)
#pragma unroll
        for (int j = 0; j < 8; j++)
#pragma unroll
            for (int e = 0; e < 4; e++) acc[i][j][e] = 0.f;

    auto tile = [&](int st, int arr) -> char* { return smg + (st * 3 + arr) * GT_B; };

    auto load_chunk = [&](int st, int kt) {
        const int k0 = kt * KCH;
#pragma unroll
        for (int arr = 0; arr < 3; arr++) {
            const f16* base =
                (arr == 0) ? Ah_ + (size_t)m0 * K :
                (arr == 1) ? Al_ + (size_t)m0 * K : Wh_ + (size_t)n0 * K;
            char* dst = tile(st, arr);
#pragma unroll
            for (int i = 0; i < 2; i++) {
                int idx = tid + i * 256;
                int r  = idx >> 2;
                int c4 = idx & 3;
                uint32_t off = sw64((uint32_t)(r * 64 + c4 * 16));
                cp16(dst + off, base + (size_t)r * K + k0 + c4 * 8);
            }
        }
    };

    load_chunk(0, 0); cpcommit();
    load_chunk(1, 1); cpcommit();

    for (int kt = 0; kt < NKT; kt++) {
        const int st = kt % 3;
        if (kt == NKT - 1) cpwait<0>(); else cpwait<1>();
        __syncthreads();

        char* sAh = tile(st, 0);
        char* sAl = tile(st, 1);
        char* sWh = tile(st, 2);
#pragma unroll
        for (int kc = 0; kc < 2; kc++) {
            const uint32_t acol = (uint32_t)((kc * 16 + a_csel) * 2);
            const uint32_t bcol = (uint32_t)((kc * 16 + b_kcol) * 2);
            uint32_t ah[2][4], al[2][4];
#pragma unroll
            for (int i = 0; i < 2; i++) {
                uint32_t off = sw64((uint32_t)((wm + i * 16 + a_row) * 64) + acol);
                ldsm_x4(ah[i][0], ah[i][1], ah[i][2], ah[i][3], smaddr(sAh + off));
                ldsm_x4(al[i][0], al[i][1], al[i][2], al[i][3], smaddr(sAl + off));
            }
            uint32_t bh[8][2];
#pragma unroll
            for (int jp = 0; jp < 4; jp++) {
                uint32_t off = sw64((uint32_t)((wn + jp * 16 + b_nrow) * 64) + bcol);
                ldsm_x4(bh[2 * jp][0], bh[2 * jp][1], bh[2 * jp + 1][0], bh[2 * jp + 1][1],
                        smaddr(sWh + off));
            }
#pragma unroll
            for (int i = 0; i < 2; i++)
#pragma unroll
                for (int j = 0; j < 8; j++) {
                    mma_f16(acc[i][j], ah[i], bh[j]);
                    mma_f16(acc[i][j], al[i], bh[j]);
                }
        }

        if (kt + 2 < NKT) {
            load_chunk((kt + 2) % 3, kt + 2);
            cpcommit();
        }
    }

    const int g = lane >> 2, t = lane & 3;
    if (MODE == 0) {
#pragma unroll
        for (int i = 0; i < 2; i++)
#pragma unroll
            for (int j = 0; j < 8; j++)
#pragma unroll
                for (int e = 0; e < 4; e++) {
                    int row = m0 + wm + i * 16 + g + (e >> 1) * 8;
                    int col = n0 + wn + j * 8 + 2 * t + (e & 1);
                    float val = acc[i][j][e] + bias[col];
                    int h = col / 192;
                    int rem = col - h * 192;
                    int d = rem / 3;
                    int which = rem - d * 3;
                    int bb = row >> 11;
                    int nn = row & (NSEQ - 1);
                    size_t idx = ((size_t)(bb * NH + h) * NSEQ + nn) * HD + d;
                    if (which == 0) {
                        f16 hi, lo;
                        hsplit(val * 0.125f, hi, lo);
                        g_qh[idx] = hi; g_ql[idx] = lo;
                    } else if (which == 1) {
                        g_kh[idx] = __float2half_rn(val);
                    } else {
                        g_vh[idx] = __float2half_rn(val);
                    }
                }
    } else {
#pragma unroll
        for (int i = 0; i < 2; i++)
#pragma unroll
            for (int j = 0; j < 8; j++)
#pragma unroll
                for (int e = 0; e < 4; e++) {
                    int row = m0 + wm + i * 16 + g + (e >> 1) * 8;
                    int col = n0 + wn + j * 8 + 2 * t + (e & 1);
                    Cout[(size_t)row * EMB + col] = acc[i][j][e] + bias[col];
                }
    }
}

// ---------------- flash attention (R5 structure, fp16 2-pass) ----------------
// Block = 128 q-rows of one (b,h), 8 warps. Double-buffered {Kh, Vh}.
// S = (Qh+Ql) Kh^T ; O += (Ph+Pl) Vh.
#define AT_TILE (128 * 72)
#define ATTN_SMEM ((2 + 4) * AT_TILE * 2)   // 110592 bytes

__global__ void __launch_bounds__(256) attn_f16()
{
    extern __shared__ f16 sm[];
    f16* Qh = sm;
    f16* Ql = sm + AT_TILE;
    auto buf = [&](int st, int arr) -> f16* { return sm + (2 + st * 2 + arr) * AT_TILE; };

    const int tid  = threadIdx.x;
    const int lane = tid & 31;
    const int warp = tid >> 5;
    const int bh = blockIdx.y;
    const int b  = bh >> 4;
    const int h  = bh & 15;
    const int q0 = blockIdx.x * 128;

    const f16* Qgh = g_qh + (size_t)bh * NSEQ * HD;
    const f16* Qgl = g_ql + (size_t)bh * NSEQ * HD;
    const f16* Kgh = g_kh + (size_t)bh * NSEQ * HD;
    const f16* Vgh = g_vh + (size_t)bh * NSEQ * HD;

    const int a_row = lane & 15;
    const int a_csel = (lane >> 4) * 8;
    const int b_nrow = (lane & 7) + (lane >> 4) * 8;
    const int b_kcol = ((lane >> 3) & 1) * 8;
    const int g = lane >> 2, t = lane & 3;

    auto load_kv = [&](int st, int t0) {
#pragma unroll
        for (int i = 0; i < 4; i++) {
            int s = tid + i * 256;
            int r = s >> 3;
            int c = (s & 7) * 8;
            cp16(buf(st, 0) + r * 72 + c, Kgh + (size_t)(t0 + r) * HD + c);
            cp16(buf(st, 1) + r * 72 + c, Vgh + (size_t)(t0 + r) * HD + c);
        }
    };

#pragma unroll
    for (int i = 0; i < 4; i++) {
        int s = tid + i * 256;
        int r = s >> 3;
        int c = (s & 7) * 8;
        cp16(Qh + r * 72 + c, Qgh + (size_t)(q0 + r) * HD + c);
        cp16(Ql + r * 72 + c, Qgl + (size_t)(q0 + r) * HD + c);
    }
    load_kv(0, 0);
    cpcommit();
    cpwait<0>();
    __syncthreads();

    uint32_t qh[4][4], ql[4][4];
#pragma unroll
    for (int kc = 0; kc < 4; kc++) {
        uint32_t ad = smaddr(&Qh[(16 * warp + a_row) * 72 + kc * 16 + a_csel]);
        ldsm_x4(qh[kc][0], qh[kc][1], qh[kc][2], qh[kc][3], ad);
        ad = smaddr(&Ql[(16 * warp + a_row) * 72 + kc * 16 + a_csel]);
        ldsm_x4(ql[kc][0], ql[kc][1], ql[kc][2], ql[kc][3], ad);
    }

    float oacc[8][4];
#pragma unroll
    for (int j = 0; j < 8; j++)
#pragma unroll
        for (int e = 0; e < 4; e++) oacc[j][e] = 0.f;
    float m0r = -1e30f, m1r = -1e30f, l0 = 0.f, l1 = 0.f;

    for (int ti = 0; ti < NSEQ / 128; ti++) {
        int cb = ti & 1;
        if (ti + 1 < NSEQ / 128) {
            load_kv(cb ^ 1, (ti + 1) * 128);
            cpcommit();
            cpwait<1>();
        } else {
            cpwait<0>();
        }
        __syncthreads();

        // ---- S = (Qh+Ql) Kh^T ----
        float sacc[16][4];
#pragma unroll
        for (int j = 0; j < 16; j++)
#pragma unroll
            for (int e = 0; e < 4; e++) sacc[j][e] = 0.f;

        f16* Kh = buf(cb, 0);
#pragma unroll
        for (int kc = 0; kc < 4; kc++) {
#pragma unroll
            for (int jp = 0; jp < 8; jp++) {
                uint32_t bh4[4];
                uint32_t ad = smaddr(&Kh[(jp * 16 + b_nrow) * 72 + kc * 16 + b_kcol]);
                ldsm_x4(bh4[0], bh4[1], bh4[2], bh4[3], ad);
                mma_f16(sacc[2 * jp],     qh[kc], &bh4[0]);
                mma_f16(sacc[2 * jp],     ql[kc], &bh4[0]);
                mma_f16(sacc[2 * jp + 1], qh[kc], &bh4[2]);
                mma_f16(sacc[2 * jp + 1], ql[kc], &bh4[2]);
            }
        }

        // ---- register softmax ----
        float mx0 = -1e30f, mx1 = -1e30f;
#pragma unroll
        for (int j = 0; j < 16; j++) {
            mx0 = fmaxf(mx0, fmaxf(sacc[j][0], sacc[j][1]));
            mx1 = fmaxf(mx1, fmaxf(sacc[j][2], sacc[j][3]));
        }
        mx0 = fmaxf(mx0, __shfl_xor_sync(0xffffffffu, mx0, 1));
        mx0 = fmaxf(mx0, __shfl_xor_sync(0xffffffffu, mx0, 2));
        mx1 = fmaxf(mx1, __shfl_xor_sync(0xffffffffu, mx1, 1));
        mx1 = fmaxf(mx1, __shfl_xor_sync(0xffffffffu, mx1, 2));
        float mn0 = fmaxf(m0r, mx0), mn1 = fmaxf(m1r, mx1);
        float al0 = fast_exp(m0r - mn0), al1 = fast_exp(m1r - mn1);
        m0r = mn0; m1r = mn1;

        float s0 = 0.f, s1 = 0.f;
        uint32_t aph[8][4], apl[8][4];
#pragma unroll
        for (int j2 = 0; j2 < 8; j2++) {
            float p[8];
            p[0] = fast_exp(sacc[2 * j2][0] - mn0);
            p[1] = fast_exp(sacc[2 * j2][1] - mn0);
            p[2] = fast_exp(sacc[2 * j2][2] - mn1);
            p[3] = fast_exp(sacc[2 * j2][3] - mn1);
            p[4] = fast_exp(sacc[2 * j2 + 1][0] - mn0);
            p[5] = fast_exp(sacc[2 * j2 + 1][1] - mn0);
            p[6] = fast_exp(sacc[2 * j2 + 1][2] - mn1);
            p[7] = fast_exp(sacc[2 * j2 + 1][3] - mn1);
            s0 += p[0] + p[1] + p[4] + p[5];
            s1 += p[2] + p[3] + p[6] + p[7];
            f16 hb[8]; float lf[8];
#pragma unroll
            for (int e = 0; e < 8; e++) {
                hb[e] = __float2half_rn(p[e]);
                lf[e] = p[e] - __half2float(hb[e]);
            }
            aph[j2][0] = pack2h(hb[0], hb[1]);
            aph[j2][1] = pack2h(hb[2], hb[3]);
            aph[j2][2] = pack2h(hb[4], hb[5]);
            aph[j2][3] = pack2h(hb[6], hb[7]);
            apl[j2][0] = pack2h(__float2half_rn(lf[0]), __float2half_rn(lf[1]));
            apl[j2][1] = pack2h(__float2half_rn(lf[2]), __float2half_rn(lf[3]));
            apl[j2][2] = pack2h(__float2half_rn(lf[4]), __float2half_rn(lf[5]));
            apl[j2][3] = pack2h(__float2half_rn(lf[6]), __float2half_rn(lf[7]));
        }
        s0 += __shfl_xor_sync(0xffffffffu, s0, 1);
        s0 += __shfl_xor_sync(0xffffffffu, s0, 2);
        s1 += __shfl_xor_sync(0xffffffffu, s1, 1);
        s1 += __shfl_xor_sync(0xffffffffu, s1, 2);
        l0 = l0 * al0 + s0;
        l1 = l1 * al1 + s1;

#pragma unroll
        for (int j = 0; j < 8; j++) {
            oacc[j][0] *= al0; oacc[j][1] *= al0;
            oacc[j][2] *= al1; oacc[j][3] *= al1;
        }

        // ---- O += (Ph+Pl) Vh ----
        f16* Vh = buf(cb, 1);
#pragma unroll
        for (int kc = 0; kc < 8; kc++) {
#pragma unroll
            for (int jp = 0; jp < 4; jp++) {
                uint32_t bh4[4];
                uint32_t ad = smaddr(&Vh[(kc * 16 + a_row) * 72 + jp * 16 + a_csel]);
                ldsm_x4t(bh4[0], bh4[1], bh4[2], bh4[3], ad);
                mma_f16(oacc[2 * jp],     aph[kc], &bh4[0]);
                mma_f16(oacc[2 * jp],     apl[kc], &bh4[0]);
                mma_f16(oacc[2 * jp + 1], aph[kc], &bh4[2]);
                mma_f16(oacc[2 * jp + 1], apl[kc], &bh4[2]);
            }
        }
        __syncthreads();
    }

    // ---- epilogue: split(O/l) -> g_atth/g_attl at [b, q, h*64+d] ----
    float inv0 = 1.0f / l0;
    float inv1 = 1.0f / l1;
#pragma unroll
    for (int j = 0; j < 8; j++)
#pragma unroll
        for (int e = 0; e < 4; e++) {
            int row = 16 * warp + g + (e >> 1) * 8;
            int col = j * 8 + 2 * t + (e & 1);
            float val = oacc[j][e] * ((e >> 1) ? inv1 : inv0);
            size_t off = ((size_t)b * NSEQ + q0 + row) * EMB + h * HD + col;
            f16 hi, lo;
            hsplit(val, hi, lo);
            g_atth[off] = hi;
            g_attl[off] = lo;
        }
}

// ---------------------------------------------------------------------------
extern "C" void kernel_launch(void* const* d_in, const int* in_sizes, int n_in,
                              void* d_out, int out_size)
{
    const float* x      = (const float*)d_in[0];
    const float* w_qkv  = (const float*)d_in[1];
    const float* b_qkv  = (const float*)d_in[2];
    const float* w_proj = (const float*)d_in[3];
    const float* b_proj = (const float*)d_in[4];
    float* out = (float*)d_out;

    cudaFuncSetAttribute(gemm_f16<0>, cudaFuncAttributeMaxDynamicSharedMemorySize, GEMM_SMEM);
    cudaFuncSetAttribute(gemm_f16<1>, cudaFuncAttributeMaxDynamicSharedMemorySize, GEMM_SMEM);
    cudaFuncSetAttribute(attn_f16, cudaFuncAttributeMaxDynamicSharedMemorySize, (int)ATTN_SMEM);

    f16 *xh, *xl, *wqh, *wph, *atth, *attl;
    cudaGetSymbolAddress((void**)&xh,  g_xh);  cudaGetSymbolAddress((void**)&xl,  g_xl);
    cudaGetSymbolAddress((void**)&wqh, g_wqh); cudaGetSymbolAddress((void**)&wph, g_wph);
    cudaGetSymbolAddress((void**)&atth, g_atth); cudaGetSymbolAddress((void**)&attl, g_attl);

    // 1) split x to fp16 hi/lo; round weights to fp16
    split2_kernel<<<(NTOK * EMB) / 1024, 256>>>((const float4*)x,
        (__half2*)xh, (__half2*)xl, NTOK * EMB / 4);
    round1_kernel<<<(QKVN * EMB) / 1024, 256>>>((const float4*)w_qkv,
        (__half2*)wqh, QKVN * EMB / 4);
    round1_kernel<<<(EMB * EMB) / 1024, 256>>>((const float4*)w_proj,
        (__half2*)wph, EMB * EMB / 4);

    // 2) QKV projection + scatter (q pre-scaled by 1/8, split fp16 hi/lo)
    gemm_f16<0><<<dim3(QKVN / 128, NTOK / 128), 256, GEMM_SMEM>>>(
        xh, xl, wqh, b_qkv, nullptr);

    // 3) flash attention
    attn_f16<<<dim3(NSEQ / 128, BB * NH), 256, ATTN_SMEM>>>();

    // 4) output projection
    gemm_f16<1><<<dim3(EMB / 128, NTOK / 128), 256, GEMM_SMEM>>>(
        atth, attl, wph, b_proj, out);
}

// round 8
// speedup vs baseline: 2.3976x; 1.0698x over previous
#include <cuda_runtime.h>
#include <cuda_fp16.h>
#include <math.h>
#include <stdint.h>

#define BB   4
#define NSEQ 2048
#define EMB  1024
#define NH   16
#define HD   64
#define NTOK (BB * NSEQ)      // 8192
#define QKVN (3 * EMB)        // 3072

typedef __half f16;

// ---------------- scratch (__device__ globals; allocation-free) -------------
__device__ f16 g_xh[NTOK * EMB],  g_xl[NTOK * EMB];
__device__ f16 g_wqh[QKVN * EMB];
__device__ f16 g_wph[EMB * EMB];
__device__ f16 g_qh[BB*NH*NSEQ*HD], g_ql[BB*NH*NSEQ*HD];
__device__ f16 g_kh[BB*NH*NSEQ*HD];
__device__ f16 g_vh[BB*NH*NSEQ*HD];
__device__ f16 g_atth[NTOK * EMB];

// ---------------- helpers ----------------------------------------------------
__device__ __forceinline__ uint32_t smaddr(const void* p) {
    return (uint32_t)__cvta_generic_to_shared(p);
}
__device__ __forceinline__ void ldsm_x4(uint32_t& r0, uint32_t& r1, uint32_t& r2,
                                        uint32_t& r3, uint32_t a) {
    asm volatile("ldmatrix.sync.aligned.m8n8.x4.shared.b16 {%0,%1,%2,%3},[%4];\n"
                 : "=r"(r0), "=r"(r1), "=r"(r2), "=r"(r3) : "r"(a));
}
__device__ __forceinline__ void ldsm_x4t(uint32_t& r0, uint32_t& r1, uint32_t& r2,
                                         uint32_t& r3, uint32_t a) {
    asm volatile("ldmatrix.sync.aligned.m8n8.x4.trans.shared.b16 {%0,%1,%2,%3},[%4];\n"
                 : "=r"(r0), "=r"(r1), "=r"(r2), "=r"(r3) : "r"(a));
}
__device__ __forceinline__ void mma_f16(float c[4], const uint32_t a[4],
                                        const uint32_t b[2]) {
    asm volatile(
        "mma.sync.aligned.m16n8k16.row.col.f32.f16.f16.f32 "
        "{%0,%1,%2,%3}, {%4,%5,%6,%7}, {%8,%9}, {%0,%1,%2,%3};\n"
        : "+f"(c[0]), "+f"(c[1]), "+f"(c[2]), "+f"(c[3])
        : "r"(a[0]), "r"(a[1]), "r"(a[2]), "r"(a[3]), "r"(b[0]), "r"(b[1]));
}
__device__ __forceinline__ void hsplit(float v, f16& h, f16& l) {
    h = __float2half_rn(v);
    l = __float2half_rn(v - __half2float(h));
}
__device__ __forceinline__ uint32_t pack2h(f16 a, f16 b) {
    __half2 t; t.x = a; t.y = b;
    return *(uint32_t*)&t;
}
// FMA-pipe exp (no MUFU). Valid for x <= 0 (clamped below).
__device__ __forceinline__ float fast_exp(float x) {
    x = fmaxf(x, -86.0f);
    float y = x * 1.4426950408889634f;
    float r = rintf(y);
    float f = y - r;
    float p = 0.00133819f;
    p = fmaf(p, f, 0.00961804f);
    p = fmaf(p, f, 0.05550411f);
    p = fmaf(p, f, 0.24022651f);
    p = fmaf(p, f, 0.69314718f);
    p = fmaf(p, f, 1.0f);
    int e = (int)r;
    return p * __int_as_float((e + 127) << 23);
}
__device__ __forceinline__ void cp16(void* dst, const void* src) {
    asm volatile("cp.async.cg.shared.global [%0],[%1],16;\n"
                 :: "r"(smaddr(dst)), "l"(src));
}
__device__ __forceinline__ void cpcommit() {
    asm volatile("cp.async.commit_group;\n");
}
template <int N>
__device__ __forceinline__ void cpwait() {
    asm volatile("cp.async.wait_group %0;\n" :: "n"(N));
}
__device__ __forceinline__ uint32_t sw64(uint32_t off) {
    return off ^ ((off >> 3) & 0x30);
}

// ---------------- split kernels (fp32 -> fp16 hi/lo or hi only) --------------
__global__ void __launch_bounds__(256) split2_kernel(
    const float4* __restrict__ in, __half2* __restrict__ h,
    __half2* __restrict__ l, int n4)
{
    int i = blockIdx.x * 256 + threadIdx.x;
    if (i >= n4) return;
    float4 v = in[i];
    f16 h0, l0, h1, l1, h2, l2, h3, l3;
    hsplit(v.x, h0, l0); hsplit(v.y, h1, l1);
    hsplit(v.z, h2, l2); hsplit(v.w, h3, l3);
    __half2 t;
    t.x = h0; t.y = h1; h[2 * i] = t;
    t.x = h2; t.y = h3; h[2 * i + 1] = t;
    t.x = l0; t.y = l1; l[2 * i] = t;
    t.x = l2; t.y = l3; l[2 * i + 1] = t;
}
__global__ void __launch_bounds__(256) round1_kernel(
    const float4* __restrict__ in, __half2* __restrict__ h, int n4)
{
    int i = blockIdx.x * 256 + threadIdx.x;
    if (i >= n4) return;
    float4 v = in[i];
    __half2 t;
    t.x = __float2half_rn(v.x); t.y = __float2half_rn(v.y); h[2 * i] = t;
    t.x = __float2half_rn(v.z); t.y = __float2half_rn(v.w); h[2 * i + 1] = t;
}

// ---------------- GEMM (NT, fp16, mma.sync) -----------------------------------
// C = (Ah [+ Al]) * Wh^T. 128x128 tile, K-chunks of 32, 3-stage cp.async.
// APASS = number of A passes (2 = hi/lo split, 1 = single).
#define KCH      32
#define NKT      (EMB / KCH)          // 32
#define GT_B     (128 * 64)           // 8 KB per array per stage
#define G_STAGES 3
#define GEMM_SMEM (G_STAGES * 3 * GT_B)  // 73728 (sized for 3 arrays)

template <int MODE, int APASS>
__global__ void __launch_bounds__(256, 2) gemm_f16(
    const f16* __restrict__ Ah_, const f16* __restrict__ Al_,
    const f16* __restrict__ Wh_,
    const float* __restrict__ bias, float* __restrict__ Cout)
{
    constexpr int K = EMB;
    extern __shared__ char smg[];

    const int tid  = threadIdx.x;
    const int lane = tid & 31;
    const int warp = tid >> 5;
    const int m0 = blockIdx.y * 128;
    const int n0 = blockIdx.x * 128;
    const int wm = (warp >> 1) * 32;
    const int wn = (warp & 1) * 64;

    const int a_row = lane & 15;
    const int a_csel = (lane >> 4) * 8;
    const int b_nrow = (lane & 7) + (lane >> 4) * 8;
    const int b_kcol = ((lane >> 3) & 1) * 8;

    float acc[2][8][4];
#pragma unroll
    for (int i = 0; i < 2; i++)
#pragma unroll
        for (int j = 0; j < 8; j++)
#pragma unroll
            for (int e = 0; e < 4; e++) acc[i][j][e] = 0.f;

    auto tile = [&](int st, int arr) -> char* { return smg + (st * 3 + arr) * GT_B; };

    auto load_chunk = [&](int st, int kt) {
        const int k0 = kt * KCH;
#pragma unroll
        for (int arr = 0; arr < 3; arr++) {
            if (APASS == 1 && arr == 1) continue;
            const f16* base =
                (arr == 0) ? Ah_ + (size_t)m0 * K :
                (arr == 1) ? Al_ + (size_t)m0 * K : Wh_ + (size_t)n0 * K;
            char* dst = tile(st, arr);
#pragma unroll
            for (int i = 0; i < 2; i++) {
                int idx = tid + i * 256;
                int r  = idx >> 2;
                int c4 = idx & 3;
                uint32_t off = sw64((uint32_t)(r * 64 + c4 * 16));
                cp16(dst + off, base + (size_t)r * K + k0 + c4 * 8);
            }
        }
    };

    load_chunk(0, 0); cpcommit();
    load_chunk(1, 1); cpcommit();

    for (int kt = 0; kt < NKT; kt++) {
        const int st = kt % 3;
        if (kt == NKT - 1) cpwait<0>(); else cpwait<1>();
        __syncthreads();

        char* sAh = tile(st, 0);
        char* sAl = tile(st, 1);
        char* sWh = tile(st, 2);
#pragma unroll
        for (int kc = 0; kc < 2; kc++) {
            const uint32_t acol = (uint32_t)((kc * 16 + a_csel) * 2);
            const uint32_t bcol = (uint32_t)((kc * 16 + b_kcol) * 2);
            uint32_t ah[2][4], al[2][4];
#pragma unroll
            for (int i = 0; i < 2; i++) {
                uint32_t off = sw64((uint32_t)((wm + i * 16 + a_row) * 64) + acol);
                ldsm_x4(ah[i][0], ah[i][1], ah[i][2], ah[i][3], smaddr(sAh + off));
                if (APASS == 2)
                    ldsm_x4(al[i][0], al[i][1], al[i][2], al[i][3], smaddr(sAl + off));
            }
            uint32_t bh[8][2];
#pragma unroll
            for (int jp = 0; jp < 4; jp++) {
                uint32_t off = sw64((uint32_t)((wn + jp * 16 + b_nrow) * 64) + bcol);
                ldsm_x4(bh[2 * jp][0], bh[2 * jp][1], bh[2 * jp + 1][0], bh[2 * jp + 1][1],
                        smaddr(sWh + off));
            }
#pragma unroll
            for (int i = 0; i < 2; i++)
#pragma unroll
                for (int j = 0; j < 8; j++) {
                    mma_f16(acc[i][j], ah[i], bh[j]);
                    if (APASS == 2) mma_f16(acc[i][j], al[i], bh[j]);
                }
        }

        if (kt + 2 < NKT) {
            load_chunk((kt + 2) % 3, kt + 2);
            cpcommit();
        }
    }

    const int g = lane >> 2, t = lane & 3;
    if (MODE == 0) {
#pragma unroll
        for (int i = 0; i < 2; i++)
#pragma unroll
            for (int j = 0; j < 8; j++)
#pragma unroll
                for (int e = 0; e < 4; e++) {
                    int row = m0 + wm + i * 16 + g + (e >> 1) * 8;
                    int col = n0 + wn + j * 8 + 2 * t + (e & 1);
                    float val = acc[i][j][e] + bias[col];
                    int h = col / 192;
                    int rem = col - h * 192;
                    int d = rem / 3;
                    int which = rem - d * 3;
                    int bb = row >> 11;
                    int nn = row & (NSEQ - 1);
                    size_t idx = ((size_t)(bb * NH + h) * NSEQ + nn) * HD + d;
                    if (which == 0) {
                        f16 hi, lo;
                        hsplit(val * 0.125f, hi, lo);
                        g_qh[idx] = hi; g_ql[idx] = lo;
                    } else if (which == 1) {
                        g_kh[idx] = __float2half_rn(val);
                    } else {
                        g_vh[idx] = __float2half_rn(val);
                    }
                }
    } else {
#pragma unroll
        for (int i = 0; i < 2; i++)
#pragma unroll
            for (int j = 0; j < 8; j++)
#pragma unroll
                for (int e = 0; e < 4; e++) {
                    int row = m0 + wm + i * 16 + g + (e >> 1) * 8;
                    int col = n0 + wn + j * 8 + 2 * t + (e & 1);
                    Cout[(size_t)row * EMB + col] = acc[i][j][e] + bias[col];
                }
    }
}

// ---------------- flash attention (fp16; S 2-pass, PV 1-pass) ----------------
// Block = 128 q-rows of one (b,h), 8 warps. Double-buffered {Kh, Vh}.
// S = (Qh+Ql) Kh^T ; O += Ph Vh.
#define AT_TILE (128 * 72)
#define ATTN_SMEM ((2 + 4) * AT_TILE * 2)   // 110592 bytes

__global__ void __launch_bounds__(256) attn_f16()
{
    extern __shared__ f16 sm[];
    f16* Qh = sm;
    f16* Ql = sm + AT_TILE;
    auto buf = [&](int st, int arr) -> f16* { return sm + (2 + st * 2 + arr) * AT_TILE; };

    const int tid  = threadIdx.x;
    const int lane = tid & 31;
    const int warp = tid >> 5;
    const int bh = blockIdx.y;
    const int b  = bh >> 4;
    const int h  = bh & 15;
    const int q0 = blockIdx.x * 128;

    const f16* Qgh = g_qh + (size_t)bh * NSEQ * HD;
    const f16* Qgl = g_ql + (size_t)bh * NSEQ * HD;
    const f16* Kgh = g_kh + (size_t)bh * NSEQ * HD;
    const f16* Vgh = g_vh + (size_t)bh * NSEQ * HD;

    const int a_row = lane & 15;
    const int a_csel = (lane >> 4) * 8;
    const int b_nrow = (lane & 7) + (lane >> 4) * 8;
    const int b_kcol = ((lane >> 3) & 1) * 8;
    const int g = lane >> 2, t = lane & 3;

    auto load_kv = [&](int st, int t0) {
#pragma unroll
        for (int i = 0; i < 4; i++) {
            int s = tid + i * 256;
            int r = s >> 3;
            int c = (s & 7) * 8;
            cp16(buf(st, 0) + r * 72 + c, Kgh + (size_t)(t0 + r) * HD + c);
            cp16(buf(st, 1) + r * 72 + c, Vgh + (size_t)(t0 + r) * HD + c);
        }
    };

#pragma unroll
    for (int i = 0; i < 4; i++) {
        int s = tid + i * 256;
        int r = s >> 3;
        int c = (s & 7) * 8;
        cp16(Qh + r * 72 + c, Qgh + (size_t)(q0 + r) * HD + c);
        cp16(Ql + r * 72 + c, Qgl + (size_t)(q0 + r) * HD + c);
    }
    load_kv(0, 0);
    cpcommit();
    cpwait<0>();
    __syncthreads();

    uint32_t qh[4][4], ql[4][4];
#pragma unroll
    for (int kc = 0; kc < 4; kc++) {
        uint32_t ad = smaddr(&Qh[(16 * warp + a_row) * 72 + kc * 16 + a_csel]);
        ldsm_x4(qh[kc][0], qh[kc][1], qh[kc][2], qh[kc][3], ad);
        ad = smaddr(&Ql[(16 * warp + a_row) * 72 + kc * 16 + a_csel]);
        ldsm_x4(ql[kc][0], ql[kc][1], ql[kc][2], ql[kc][3], ad);
    }

    float oacc[8][4];
#pragma unroll
    for (int j = 0; j < 8; j++)
#pragma unroll
        for (int e = 0; e < 4; e++) oacc[j][e] = 0.f;
    float m0r = -1e30f, m1r = -1e30f, l0 = 0.f, l1 = 0.f;

    for (int ti = 0; ti < NSEQ / 128; ti++) {
        int cb = ti & 1;
        if (ti + 1 < NSEQ / 128) {
            load_kv(cb ^ 1, (ti + 1) * 128);
            cpcommit();
            cpwait<1>();
        } else {
            cpwait<0>();
        }
        __syncthreads();

        // ---- S = (Qh+Ql) Kh^T ----
        float sacc[16][4];
#pragma unroll
        for (int j = 0; j < 16; j++)
#pragma unroll
            for (int e = 0; e < 4; e++) sacc[j][e] = 0.f;

        f16* Kh = buf(cb, 0);
#pragma unroll
        for (int kc = 0; kc < 4; kc++) {
#pragma unroll
            for (int jp = 0; jp < 8; jp++) {
                uint32_t bh4[4];
                uint32_t ad = smaddr(&Kh[(jp * 16 + b_nrow) * 72 + kc * 16 + b_kcol]);
                ldsm_x4(bh4[0], bh4[1], bh4[2], bh4[3], ad);
                mma_f16(sacc[2 * jp],     qh[kc], &bh4[0]);
                mma_f16(sacc[2 * jp],     ql[kc], &bh4[0]);
                mma_f16(sacc[2 * jp + 1], qh[kc], &bh4[2]);
                mma_f16(sacc[2 * jp + 1], ql[kc], &bh4[2]);
            }
        }

        // ---- register softmax ----
        float mx0 = -1e30f, mx1 = -1e30f;
#pragma unroll
        for (int j = 0; j < 16; j++) {
            mx0 = fmaxf(mx0, fmaxf(sacc[j][0], sacc[j][1]));
            mx1 = fmaxf(mx1, fmaxf(sacc[j][2], sacc[j][3]));
        }
        mx0 = fmaxf(mx0, __shfl_xor_sync(0xffffffffu, mx0, 1));
        mx0 = fmaxf(mx0, __shfl_xor_sync(0xffffffffu, mx0, 2));
        mx1 = fmaxf(mx1, __shfl_xor_sync(0xffffffffu, mx1, 1));
        mx1 = fmaxf(mx1, __shfl_xor_sync(0xffffffffu, mx1, 2));
        float mn0 = fmaxf(m0r, mx0), mn1 = fmaxf(m1r, mx1);
        float al0 = fast_exp(m0r - mn0), al1 = fast_exp(m1r - mn1);
        m0r = mn0; m1r = mn1;

        float s0 = 0.f, s1 = 0.f;
        uint32_t aph[8][4];
#pragma unroll
        for (int j2 = 0; j2 < 8; j2++) {
            float p[8];
            p[0] = fast_exp(sacc[2 * j2][0] - mn0);
            p[1] = fast_exp(sacc[2 * j2][1] - mn0);
            p[2] = fast_exp(sacc[2 * j2][2] - mn1);
            p[3] = fast_exp(sacc[2 * j2][3] - mn1);
            p[4] = fast_exp(sacc[2 * j2 + 1][0] - mn0);
            p[5] = fast_exp(sacc[2 * j2 + 1][1] - mn0);
            p[6] = fast_exp(sacc[2 * j2 + 1][2] - mn1);
            p[7] = fast_exp(sacc[2 * j2 + 1][3] - mn1);
            s0 += p[0] + p[1] + p[4] + p[5];
            s1 += p[2] + p[3] + p[6] + p[7];
            aph[j2][0] = pack2h(__float2half_rn(p[0]), __float2half_rn(p[1]));
            aph[j2][1] = pack2h(__float2half_rn(p[2]), __float2half_rn(p[3]));
            aph[j2][2] = pack2h(__float2half_rn(p[4]), __float2half_rn(p[5]));
            aph[j2][3] = pack2h(__float2half_rn(p[6]), __float2half_rn(p[7]));
        }
        s0 += __shfl_xor_sync(0xffffffffu, s0, 1);
        s0 += __shfl_xor_sync(0xffffffffu, s0, 2);
        s1 += __shfl_xor_sync(0xffffffffu, s1, 1);
        s1 += __shfl_xor_sync(0xffffffffu, s1, 2);
        l0 = l0 * al0 + s0;
        l1 = l1 * al1 + s1;

#pragma unroll
        for (int j = 0; j < 8; j++) {
            oacc[j][0] *= al0; oacc[j][1] *= al0;
            oacc[j][2] *= al1; oacc[j][3] *= al1;
        }

        // ---- O += Ph Vh (1-pass) ----
        f16* Vh = buf(cb, 1);
#pragma unroll
        for (int kc = 0; kc < 8; kc++) {
#pragma unroll
            for (int jp = 0; jp < 4; jp++) {
                uint32_t bh4[4];
                uint32_t ad = smaddr(&Vh[(kc * 16 + a_row) * 72 + jp * 16 + a_csel]);
                ldsm_x4t(bh4[0], bh4[1], bh4[2], bh4[3], ad);
                mma_f16(oacc[2 * jp],     aph[kc], &bh4[0]);
                mma_f16(oacc[2 * jp + 1], aph[kc], &bh4[2]);
            }
        }
        __syncthreads();
    }

    // ---- epilogue: round(O/l) -> g_atth at [b, q, h*64+d] ----
    float inv0 = 1.0f / l0;
    float inv1 = 1.0f / l1;
#pragma unroll
    for (int j = 0; j < 8; j++)
#pragma unroll
        for (int e = 0; e < 4; e++) {
            int row = 16 * warp + g + (e >> 1) * 8;
            int col = j * 8 + 2 * t + (e & 1);
            float val = oacc[j][e] * ((e >> 1) ? inv1 : inv0);
            size_t off = ((size_t)b * NSEQ + q0 + row) * EMB + h * HD + col;
            g_atth[off] = __float2half_rn(val);
        }
}

// ---------------------------------------------------------------------------
extern "C" void kernel_launch(void* const* d_in, const int* in_sizes, int n_in,
                              void* d_out, int out_size)
{
    const float* x      = (const float*)d_in[0];
    const float* w_qkv  = (const float*)d_in[1];
    const float* b_qkv  = (const float*)d_in[2];
    const float* w_proj = (const float*)d_in[3];
    const float* b_proj = (const float*)d_in[4];
    float* out = (float*)d_out;

    cudaFuncSetAttribute((const void*)gemm_f16<0, 2>,
                         cudaFuncAttributeMaxDynamicSharedMemorySize, GEMM_SMEM);
    cudaFuncSetAttribute((const void*)gemm_f16<1, 1>,
                         cudaFuncAttributeMaxDynamicSharedMemorySize, GEMM_SMEM);
    cudaFuncSetAttribute(attn_f16, cudaFuncAttributeMaxDynamicSharedMemorySize, (int)ATTN_SMEM);

    f16 *xh, *xl, *wqh, *wph, *atth;
    cudaGetSymbolAddress((void**)&xh,  g_xh);  cudaGetSymbolAddress((void**)&xl,  g_xl);
    cudaGetSymbolAddress((void**)&wqh, g_wqh); cudaGetSymbolAddress((void**)&wph, g_wph);
    cudaGetSymbolAddress((void**)&atth, g_atth);

    // 1) split x to fp16 hi/lo; round weights to fp16
    split2_kernel<<<(NTOK * EMB) / 1024, 256>>>((const float4*)x,
        (__half2*)xh, (__half2*)xl, NTOK * EMB / 4);
    round1_kernel<<<(QKVN * EMB) / 1024, 256>>>((const float4*)w_qkv,
        (__half2*)wqh, QKVN * EMB / 4);
    round1_kernel<<<(EMB * EMB) / 1024, 256>>>((const float4*)w_proj,
        (__half2*)wph, EMB * EMB / 4);

    // 2) QKV projection + scatter (q pre-scaled by 1/8, split fp16 hi/lo)
    gemm_f16<0, 2><<<dim3(QKVN / 128, NTOK / 128), 256, GEMM_SMEM>>>(
        xh, xl, wqh, b_qkv, nullptr);

    // 3) flash attention
    attn_f16<<<dim3(NSEQ / 128, BB * NH), 256, ATTN_SMEM>>>();

    // 4) output projection (1-pass A)
    gemm_f16<1, 1><<<dim3(EMB / 128, NTOK / 128), 256, GEMM_SMEM>>>(
        atth, nullptr, wph, b_proj, out);
}

// round 9
// speedup vs baseline: 2.9890x; 1.2467x over previous
#include <cuda_runtime.h>
#include <cuda_fp16.h>
#include <math.h>
#include <stdint.h>

#define BB   4
#define NSEQ 2048
#define EMB  1024
#define NH   16
#define HD   64
#define NTOK (BB * NSEQ)      // 8192
#define QKVN (3 * EMB)        // 3072

typedef __half f16;

// ---------------- scratch (__device__ globals; allocation-free) -------------
__device__ f16 g_xh[NTOK * EMB];
__device__ f16 g_wqh[QKVN * EMB];
__device__ f16 g_wph[EMB * EMB];
__device__ f16 g_qh[BB*NH*NSEQ*HD];
__device__ f16 g_kh[BB*NH*NSEQ*HD];
__device__ f16 g_vh[BB*NH*NSEQ*HD];
__device__ f16 g_atth[NTOK * EMB];

// ---------------- helpers ----------------------------------------------------
__device__ __forceinline__ uint32_t smaddr(const void* p) {
    return (uint32_t)__cvta_generic_to_shared(p);
}
__device__ __forceinline__ void ldsm_x4(uint32_t& r0, uint32_t& r1, uint32_t& r2,
                                        uint32_t& r3, uint32_t a) {
    asm volatile("ldmatrix.sync.aligned.m8n8.x4.shared.b16 {%0,%1,%2,%3},[%4];\n"
                 : "=r"(r0), "=r"(r1), "=r"(r2), "=r"(r3) : "r"(a));
}
__device__ __forceinline__ void ldsm_x4t(uint32_t& r0, uint32_t& r1, uint32_t& r2,
                                         uint32_t& r3, uint32_t a) {
    asm volatile("ldmatrix.sync.aligned.m8n8.x4.trans.shared.b16 {%0,%1,%2,%3},[%4];\n"
                 : "=r"(r0), "=r"(r1), "=r"(r2), "=r"(r3) : "r"(a));
}
__device__ __forceinline__ void mma_f16(float c[4], const uint32_t a[4],
                                        const uint32_t b[2]) {
    asm volatile(
        "mma.sync.aligned.m16n8k16.row.col.f32.f16.f16.f32 "
        "{%0,%1,%2,%3}, {%4,%5,%6,%7}, {%8,%9}, {%0,%1,%2,%3};\n"
        : "+f"(c[0]), "+f"(c[1]), "+f"(c[2]), "+f"(c[3])
        : "r"(a[0]), "r"(a[1]), "r"(a[2]), "r"(a[3]), "r"(b[0]), "r"(b[1]));
}
__device__ __forceinline__ uint32_t pack2h(f16 a, f16 b) {
    __half2 t; t.x = a; t.y = b;
    return *(uint32_t*)&t;
}
// FMA-pipe exp (no MUFU). Valid for x <= 0 (clamped below).
__device__ __forceinline__ float fast_exp(float x) {
    x = fmaxf(x, -86.0f);
    float y = x * 1.4426950408889634f;
    float r = rintf(y);
    float f = y - r;
    float p = 0.00133819f;
    p = fmaf(p, f, 0.00961804f);
    p = fmaf(p, f, 0.05550411f);
    p = fmaf(p, f, 0.24022651f);
    p = fmaf(p, f, 0.69314718f);
    p = fmaf(p, f, 1.0f);
    int e = (int)r;
    return p * __int_as_float((e + 127) << 23);
}
__device__ __forceinline__ void cp16(void* dst, const void* src) {
    asm volatile("cp.async.cg.shared.global [%0],[%1],16;\n"
                 :: "r"(smaddr(dst)), "l"(src));
}
__device__ __forceinline__ void cpcommit() {
    asm volatile("cp.async.commit_group;\n");
}
template <int N>
__device__ __forceinline__ void cpwait() {
    asm volatile("cp.async.wait_group %0;\n" :: "n"(N));
}
__device__ __forceinline__ uint32_t sw64(uint32_t off) {
    return off ^ ((off >> 3) & 0x30);
}

// ---------------- round kernel (fp32 -> fp16) --------------------------------
__global__ void __launch_bounds__(256) round1_kernel(
    const float4* __restrict__ in, __half2* __restrict__ h, int n4)
{
    int i = blockIdx.x * 256 + threadIdx.x;
    if (i >= n4) return;
    float4 v = in[i];
    __half2 t;
    t.x = __float2half_rn(v.x); t.y = __float2half_rn(v.y); h[2 * i] = t;
    t.x = __float2half_rn(v.z); t.y = __float2half_rn(v.w); h[2 * i + 1] = t;
}

// ---------------- GEMM (NT, fp16 1-pass, mma.sync) ----------------------------
// C = Ah * Wh^T. 128x128 tile, K-chunks of 32, 3-stage cp.async.
#define KCH      32
#define NKT      (EMB / KCH)          // 32
#define GT_B     (128 * 64)           // 8 KB per array per stage
#define G_STAGES 3
#define GEMM_SMEM (G_STAGES * 2 * GT_B)  // 49152

template <int MODE>
__global__ void __launch_bounds__(256, 2) gemm_f16(
    const f16* __restrict__ Ah_, const f16* __restrict__ Wh_,
    const float* __restrict__ bias, float* __restrict__ Cout)
{
    constexpr int K = EMB;
    extern __shared__ char smg[];

    const int tid  = threadIdx.x;
    const int lane = tid & 31;
    const int warp = tid >> 5;
    const int m0 = blockIdx.y * 128;
    const int n0 = blockIdx.x * 128;
    const int wm = (warp >> 1) * 32;
    const int wn = (warp & 1) * 64;

    const int a_row = lane & 15;
    const int a_csel = (lane >> 4) * 8;
    const int b_nrow = (lane & 7) + (lane >> 4) * 8;
    const int b_kcol = ((lane >> 3) & 1) * 8;

    float acc[2][8][4];
#pragma unroll
    for (int i = 0; i < 2; i++)
#pragma unroll
        for (int j = 0; j < 8; j++)
#pragma unroll
            for (int e = 0; e < 4; e++) acc[i][j][e] = 0.f;

    auto tile = [&](int st, int arr) -> char* { return smg + (st * 2 + arr) * GT_B; };

    auto load_chunk = [&](int st, int kt) {
        const int k0 = kt * KCH;
#pragma unroll
        for (int arr = 0; arr < 2; arr++) {
            const f16* base =
                (arr == 0) ? Ah_ + (size_t)m0 * K : Wh_ + (size_t)n0 * K;
            char* dst = tile(st, arr);
#pragma unroll
            for (int i = 0; i < 2; i++) {
                int idx = tid + i * 256;
                int r  = idx >> 2;
                int c4 = idx & 3;
                uint32_t off = sw64((uint32_t)(r * 64 + c4 * 16));
                cp16(dst + off, base + (size_t)r * K + k0 + c4 * 8);
            }
        }
    };

    load_chunk(0, 0); cpcommit();
    load_chunk(1, 1); cpcommit();

    for (int kt = 0; kt < NKT; kt++) {
        const int st = kt % 3;
        if (kt == NKT - 1) cpwait<0>(); else cpwait<1>();
        __syncthreads();

        char* sAh = tile(st, 0);
        char* sWh = tile(st, 1);
#pragma unroll
        for (int kc = 0; kc < 2; kc++) {
            const uint32_t acol = (uint32_t)((kc * 16 + a_csel) * 2);
            const uint32_t bcol = (uint32_t)((kc * 16 + b_kcol) * 2);
            uint32_t ah[2][4];
#pragma unroll
            for (int i = 0; i < 2; i++) {
                uint32_t off = sw64((uint32_t)((wm + i * 16 + a_row) * 64) + acol);
                ldsm_x4(ah[i][0], ah[i][1], ah[i][2], ah[i][3], smaddr(sAh + off));
            }
            uint32_t bh[8][2];
#pragma unroll
            for (int jp = 0; jp < 4; jp++) {
                uint32_t off = sw64((uint32_t)((wn + jp * 16 + b_nrow) * 64) + bcol);
                ldsm_x4(bh[2 * jp][0], bh[2 * jp][1], bh[2 * jp + 1][0], bh[2 * jp + 1][1],
                        smaddr(sWh + off));
            }
#pragma unroll
            for (int i = 0; i < 2; i++)
#pragma unroll
                for (int j = 0; j < 8; j++)
                    mma_f16(acc[i][j], ah[i], bh[j]);
        }

        if (kt + 2 < NKT) {
            load_chunk((kt + 2) % 3, kt + 2);
            cpcommit();
        }
    }

    const int g = lane >> 2, t = lane & 3;
    if (MODE == 0) {
#pragma unroll
        for (int i = 0; i < 2; i++)
#pragma unroll
            for (int j = 0; j < 8; j++)
#pragma unroll
                for (int e = 0; e < 4; e++) {
                    int row = m0 + wm + i * 16 + g + (e >> 1) * 8;
                    int col = n0 + wn + j * 8 + 2 * t + (e & 1);
                    float val = acc[i][j][e] + bias[col];
                    int h = col / 192;
                    int rem = col - h * 192;
                    int d = rem / 3;
                    int which = rem - d * 3;
                    int bb = row >> 11;
                    int nn = row & (NSEQ - 1);
                    size_t idx = ((size_t)(bb * NH + h) * NSEQ + nn) * HD + d;
                    if (which == 0)      g_qh[idx] = __float2half_rn(val * 0.125f);
                    else if (which == 1) g_kh[idx] = __float2half_rn(val);
                    else                 g_vh[idx] = __float2half_rn(val);
                }
    } else {
#pragma unroll
        for (int i = 0; i < 2; i++)
#pragma unroll
            for (int j = 0; j < 8; j++)
#pragma unroll
                for (int e = 0; e < 4; e++) {
                    int row = m0 + wm + i * 16 + g + (e >> 1) * 8;
                    int col = n0 + wn + j * 8 + 2 * t + (e & 1);
                    Cout[(size_t)row * EMB + col] = acc[i][j][e] + bias[col];
                }
    }
}

// ---------------- flash attention (fp16 1-pass S and PV) ---------------------
// Block = 128 q-rows of one (b,h), 8 warps. Double-buffered {Kh, Vh}.
#define AT_TILE (128 * 72)
#define ATTN_SMEM ((1 + 4) * AT_TILE * 2)   // 92160 bytes

__global__ void __launch_bounds__(256) attn_f16()
{
    extern __shared__ f16 sm[];
    f16* Qh = sm;
    auto buf = [&](int st, int arr) -> f16* { return sm + (1 + st * 2 + arr) * AT_TILE; };

    const int tid  = threadIdx.x;
    const int lane = tid & 31;
    const int warp = tid >> 5;
    const int bh = blockIdx.y;
    const int b  = bh >> 4;
    const int h  = bh & 15;
    const int q0 = blockIdx.x * 128;

    const f16* Qgh = g_qh + (size_t)bh * NSEQ * HD;
    const f16* Kgh = g_kh + (size_t)bh * NSEQ * HD;
    const f16* Vgh = g_vh + (size_t)bh * NSEQ * HD;

    const int a_row = lane & 15;
    const int a_csel = (lane >> 4) * 8;
    const int b_nrow = (lane & 7) + (lane >> 4) * 8;
    const int b_kcol = ((lane >> 3) & 1) * 8;
    const int g = lane >> 2, t = lane & 3;

    auto load_kv = [&](int st, int t0) {
#pragma unroll
        for (int i = 0; i < 4; i++) {
            int s = tid + i * 256;
            int r = s >> 3;
            int c = (s & 7) * 8;
            cp16(buf(st, 0) + r * 72 + c, Kgh + (size_t)(t0 + r) * HD + c);
            cp16(buf(st, 1) + r * 72 + c, Vgh + (size_t)(t0 + r) * HD + c);
        }
    };

#pragma unroll
    for (int i = 0; i < 4; i++) {
        int s = tid + i * 256;
        int r = s >> 3;
        int c = (s & 7) * 8;
        cp16(Qh + r * 72 + c, Qgh + (size_t)(q0 + r) * HD + c);
    }
    load_kv(0, 0);
    cpcommit();
    cpwait<0>();
    __syncthreads();

    uint32_t qh[4][4];
#pragma unroll
    for (int kc = 0; kc < 4; kc++) {
        uint32_t ad = smaddr(&Qh[(16 * warp + a_row) * 72 + kc * 16 + a_csel]);
        ldsm_x4(qh[kc][0], qh[kc][1], qh[kc][2], qh[kc][3], ad);
    }

    float oacc[8][4];
#pragma unroll
    for (int j = 0; j < 8; j++)
#pragma unroll
        for (int e = 0; e < 4; e++) oacc[j][e] = 0.f;
    float m0r = -1e30f, m1r = -1e30f, l0 = 0.f, l1 = 0.f;

    for (int ti = 0; ti < NSEQ / 128; ti++) {
        int cb = ti & 1;
        if (ti + 1 < NSEQ / 128) {
            load_kv(cb ^ 1, (ti + 1) * 128);
            cpcommit();
            cpwait<1>();
        } else {
            cpwait<0>();
        }
        __syncthreads();

        // ---- S = Qh Kh^T ----
        float sacc[16][4];
#pragma unroll
        for (int j = 0; j < 16; j++)
#pragma unroll
            for (int e = 0; e < 4; e++) sacc[j][e] = 0.f;

        f16* Kh = buf(cb, 0);
#pragma unroll
        for (int kc = 0; kc < 4; kc++) {
#pragma unroll
            for (int jp = 0; jp < 8; jp++) {
                uint32_t bh4[4];
                uint32_t ad = smaddr(&Kh[(jp * 16 + b_nrow) * 72 + kc * 16 + b_kcol]);
                ldsm_x4(bh4[0], bh4[1], bh4[2], bh4[3], ad);
                mma_f16(sacc[2 * jp],     qh[kc], &bh4[0]);
                mma_f16(sacc[2 * jp + 1], qh[kc], &bh4[2]);
            }
        }

        // ---- register softmax ----
        float mx0 = -1e30f, mx1 = -1e30f;
#pragma unroll
        for (int j = 0; j < 16; j++) {
            mx0 = fmaxf(mx0, fmaxf(sacc[j][0], sacc[j][1]));
            mx1 = fmaxf(mx1, fmaxf(sacc[j][2], sacc[j][3]));
        }
        mx0 = fmaxf(mx0, __shfl_xor_sync(0xffffffffu, mx0, 1));
        mx0 = fmaxf(mx0, __shfl_xor_sync(0xffffffffu, mx0, 2));
        mx1 = fmaxf(mx1, __shfl_xor_sync(0xffffffffu, mx1, 1));
        mx1 = fmaxf(mx1, __shfl_xor_sync(0xffffffffu, mx1, 2));
        float mn0 = fmaxf(m0r, mx0), mn1 = fmaxf(m1r, mx1);
        float al0 = fast_exp(m0r - mn0), al1 = fast_exp(m1r - mn1);
        m0r = mn0; m1r = mn1;

        float s0 = 0.f, s1 = 0.f;
        uint32_t aph[8][4];
#pragma unroll
        for (int j2 = 0; j2 < 8; j2++) {
            float p[8];
            p[0] = fast_exp(sacc[2 * j2][0] - mn0);
            p[1] = fast_exp(sacc[2 * j2][1] - mn0);
            p[2] = fast_exp(sacc[2 * j2][2] - mn1);
            p[3] = fast_exp(sacc[2 * j2][3] - mn1);
            p[4] = fast_exp(sacc[2 * j2 + 1][0] - mn0);
            p[5] = fast_exp(sacc[2 * j2 + 1][1] - mn0);
            p[6] = fast_exp(sacc[2 * j2 + 1][2] - mn1);
            p[7] = fast_exp(sacc[2 * j2 + 1][3] - mn1);
            s0 += p[0] + p[1] + p[4] + p[5];
            s1 += p[2] + p[3] + p[6] + p[7];
            aph[j2][0] = pack2h(__float2half_rn(p[0]), __float2half_rn(p[1]));
            aph[j2][1] = pack2h(__float2half_rn(p[2]), __float2half_rn(p[3]));
            aph[j2][2] = pack2h(__float2half_rn(p[4]), __float2half_rn(p[5]));
            aph[j2][3] = pack2h(__float2half_rn(p[6]), __float2half_rn(p[7]));
        }
        s0 += __shfl_xor_sync(0xffffffffu, s0, 1);
        s0 += __shfl_xor_sync(0xffffffffu, s0, 2);
        s1 += __shfl_xor_sync(0xffffffffu, s1, 1);
        s1 += __shfl_xor_sync(0xffffffffu, s1, 2);
        l0 = l0 * al0 + s0;
        l1 = l1 * al1 + s1;

#pragma unroll
        for (int j = 0; j < 8; j++) {
            oacc[j][0] *= al0; oacc[j][1] *= al0;
            oacc[j][2] *= al1; oacc[j][3] *= al1;
        }

        // ---- O += Ph Vh (1-pass) ----
        f16* Vh = buf(cb, 1);
#pragma unroll
        for (int kc = 0; kc < 8; kc++) {
#pragma unroll
            for (int jp = 0; jp < 4; jp++) {
                uint32_t bh4[4];
                uint32_t ad = smaddr(&Vh[(kc * 16 + a_row) * 72 + jp * 16 + a_csel]);
                ldsm_x4t(bh4[0], bh4[1], bh4[2], bh4[3], ad);
                mma_f16(oacc[2 * jp],     aph[kc], &bh4[0]);
                mma_f16(oacc[2 * jp + 1], aph[kc], &bh4[2]);
            }
        }
        __syncthreads();
    }

    // ---- epilogue: round(O/l) -> g_atth at [b, q, h*64+d] ----
    float inv0 = 1.0f / l0;
    float inv1 = 1.0f / l1;
#pragma unroll
    for (int j = 0; j < 8; j++)
#pragma unroll
        for (int e = 0; e < 4; e++) {
            int row = 16 * warp + g + (e >> 1) * 8;
            int col = j * 8 + 2 * t + (e & 1);
            float val = oacc[j][e] * ((e >> 1) ? inv1 : inv0);
            size_t off = ((size_t)b * NSEQ + q0 + row) * EMB + h * HD + col;
            g_atth[off] = __float2half_rn(val);
        }
}

// ---------------------------------------------------------------------------
extern "C" void kernel_launch(void* const* d_in, const int* in_sizes, int n_in,
                              void* d_out, int out_size)
{
    const float* x      = (const float*)d_in[0];
    const float* w_qkv  = (const float*)d_in[1];
    const float* b_qkv  = (const float*)d_in[2];
    const float* w_proj = (const float*)d_in[3];
    const float* b_proj = (const float*)d_in[4];
    float* out = (float*)d_out;

    cudaFuncSetAttribute((const void*)gemm_f16<0>,
                         cudaFuncAttributeMaxDynamicSharedMemorySize, GEMM_SMEM);
    cudaFuncSetAttribute((const void*)gemm_f16<1>,
                         cudaFuncAttributeMaxDynamicSharedMemorySize, GEMM_SMEM);
    cudaFuncSetAttribute(attn_f16, cudaFuncAttributeMaxDynamicSharedMemorySize, (int)ATTN_SMEM);

    f16 *xh, *wqh, *wph, *atth;
    cudaGetSymbolAddress((void**)&xh,  g_xh);
    cudaGetSymbolAddress((void**)&wqh, g_wqh);
    cudaGetSymbolAddress((void**)&wph, g_wph);
    cudaGetSymbolAddress((void**)&atth, g_atth);

    // 1) round inputs to fp16
    round1_kernel<<<(NTOK * EMB) / 1024, 256>>>((const float4*)x,
        (__half2*)xh, NTOK * EMB / 4);
    round1_kernel<<<(QKVN * EMB) / 1024, 256>>>((const float4*)w_qkv,
        (__half2*)wqh, QKVN * EMB / 4);
    round1_kernel<<<(EMB * EMB) / 1024, 256>>>((const float4*)w_proj,
        (__half2*)wph, EMB * EMB / 4);

    // 2) QKV projection + scatter (q pre-scaled by 1/8)
    gemm_f16<0><<<dim3(QKVN / 128, NTOK / 128), 256, GEMM_SMEM>>>(
        xh, wqh, b_qkv, nullptr);

    // 3) flash attention
    attn_f16<<<dim3(NSEQ / 128, BB * NH), 256, ATTN_SMEM>>>();

    // 4) output projection
    gemm_f16<1><<<dim3(EMB / 128, NTOK / 128), 256, GEMM_SMEM>>>(
        atth, wph, b_proj, out);
}

// round 10
// speedup vs baseline: 3.4217x; 1.1448x over previous
#include <cuda_runtime.h>
#include <cuda_fp16.h>
#include <math.h>
#include <stdint.h>

#define BB   4
#define NSEQ 2048
#define EMB  1024
#define NH   16
#define HD   64
#define NTOK (BB * NSEQ)      // 8192
#define QKVN (3 * EMB)        // 3072

typedef __half f16;

// ---------------- scratch (__device__ globals; allocation-free) -------------
__device__ f16 g_xh[NTOK * EMB];
__device__ f16 g_wqh[QKVN * EMB];
__device__ f16 g_wph[EMB * EMB];
__device__ f16 g_qh[BB*NH*NSEQ*HD];
__device__ f16 g_kh[BB*NH*NSEQ*HD];
__device__ f16 g_vh[BB*NH*NSEQ*HD];
__device__ f16 g_atth[NTOK * EMB];

// ---------------- helpers ----------------------------------------------------
__device__ __forceinline__ uint32_t smaddr(const void* p) {
    return (uint32_t)__cvta_generic_to_shared(p);
}
__device__ __forceinline__ void ldsm_x4(uint32_t& r0, uint32_t& r1, uint32_t& r2,
                                        uint32_t& r3, uint32_t a) {
    asm volatile("ldmatrix.sync.aligned.m8n8.x4.shared.b16 {%0,%1,%2,%3},[%4];\n"
                 : "=r"(r0), "=r"(r1), "=r"(r2), "=r"(r3) : "r"(a));
}
__device__ __forceinline__ void ldsm_x4t(uint32_t& r0, uint32_t& r1, uint32_t& r2,
                                         uint32_t& r3, uint32_t a) {
    asm volatile("ldmatrix.sync.aligned.m8n8.x4.trans.shared.b16 {%0,%1,%2,%3},[%4];\n"
                 : "=r"(r0), "=r"(r1), "=r"(r2), "=r"(r3) : "r"(a));
}
__device__ __forceinline__ void mma_f16(float c[4], const uint32_t a[4],
                                        const uint32_t b[2]) {
    asm volatile(
        "mma.sync.aligned.m16n8k16.row.col.f32.f16.f16.f32 "
        "{%0,%1,%2,%3}, {%4,%5,%6,%7}, {%8,%9}, {%0,%1,%2,%3};\n"
        : "+f"(c[0]), "+f"(c[1]), "+f"(c[2]), "+f"(c[3])
        : "r"(a[0]), "r"(a[1]), "r"(a[2]), "r"(a[3]), "r"(b[0]), "r"(b[1]));
}
__device__ __forceinline__ uint32_t pack2f(float a, float b) {
    __half2 t = __floats2half2_rn(a, b);
    return *(uint32_t*)&t;
}
// FMA-pipe exp (no MUFU). Valid for x <= 0 (clamped below).
__device__ __forceinline__ float fast_exp(float x) {
    x = fmaxf(x, -86.0f);
    float y = x * 1.4426950408889634f;
    float r = rintf(y);
    float f = y - r;
    float p = 0.00133819f;
    p = fmaf(p, f, 0.00961804f);
    p = fmaf(p, f, 0.05550411f);
    p = fmaf(p, f, 0.24022651f);
    p = fmaf(p, f, 0.69314718f);
    p = fmaf(p, f, 1.0f);
    int e = (int)r;
    return p * __int_as_float((e + 127) << 23);
}
__device__ __forceinline__ void cp16(void* dst, const void* src) {
    asm volatile("cp.async.cg.shared.global [%0],[%1],16;\n"
                 :: "r"(smaddr(dst)), "l"(src));
}
__device__ __forceinline__ void cpcommit() {
    asm volatile("cp.async.commit_group;\n");
}
template <int N>
__device__ __forceinline__ void cpwait() {
    asm volatile("cp.async.wait_group %0;\n" :: "n"(N));
}
// SW128 XOR swizzle for 128-byte rows (16B granularity)
__device__ __forceinline__ uint32_t sw128(uint32_t off) {
    return off ^ ((off >> 3) & 0x70);
}
// SW64 XOR swizzle for 64-byte rows
__device__ __forceinline__ uint32_t sw64(uint32_t off) {
    return off ^ ((off >> 3) & 0x30);
}

// ---------------- round kernel (fp32 -> fp16) --------------------------------
__global__ void __launch_bounds__(256) round1_kernel(
    const float4* __restrict__ in, __half2* __restrict__ h, int n4)
{
    int i = blockIdx.x * 256 + threadIdx.x;
    if (i >= n4) return;
    float4 v = in[i];
    h[2 * i]     = __floats2half2_rn(v.x, v.y);
    h[2 * i + 1] = __floats2half2_rn(v.z, v.w);
}

// ---------------- GEMM (NT, fp16 1-pass, mma.sync) ----------------------------
// C = Ah * Wh^T. 128x128 tile, K-chunks of 64, 3-stage cp.async, 2 CTAs/SM.
// 128-byte rows (64 f16), SW128 swizzle.
#define KCH      64
#define NKT      (EMB / KCH)           // 16
#define GT_B     (128 * 128)           // 16 KB per array per stage
#define G_STAGES 3
#define GEMM_SMEM (G_STAGES * 2 * GT_B)  // 98304

template <int MODE>
__global__ void __launch_bounds__(256, 2) gemm_f16(
    const f16* __restrict__ Ah_, const f16* __restrict__ Wh_,
    const float* __restrict__ bias, float* __restrict__ Cout)
{
    constexpr int K = EMB;
    extern __shared__ char smg[];

    const int tid  = threadIdx.x;
    const int lane = tid & 31;
    const int warp = tid >> 5;
    const int m0 = blockIdx.y * 128;
    const int n0 = blockIdx.x * 128;
    const int wm = (warp >> 1) * 32;
    const int wn = (warp & 1) * 64;

    const int a_row = lane & 15;
    const int a_csel = (lane >> 4) * 8;
    const int b_nrow = (lane & 7) + (lane >> 4) * 8;
    const int b_kcol = ((lane >> 3) & 1) * 8;

    float acc[2][8][4];
#pragma unroll
    for (int i = 0; i < 2; i++)
#pragma unroll
        for (int j = 0; j < 8; j++)
#pragma unroll
            for (int e = 0; e < 4; e++) acc[i][j][e] = 0.f;

    auto tile = [&](int st, int arr) -> char* { return smg + (st * 2 + arr) * GT_B; };

    auto load_chunk = [&](int st, int kt) {
        const int k0 = kt * KCH;
#pragma unroll
        for (int arr = 0; arr < 2; arr++) {
            const f16* base =
                (arr == 0) ? Ah_ + (size_t)m0 * K : Wh_ + (size_t)n0 * K;
            char* dst = tile(st, arr);
#pragma unroll
            for (int i = 0; i < 4; i++) {
                int idx = tid + i * 256;
                int r  = idx >> 3;
                int cb = (idx & 7) * 16;              // byte col 0..112
                uint32_t off = sw128((uint32_t)(r * 128 + cb));
                cp16(dst + off, base + (size_t)r * K + k0 + cb / 2);
            }
        }
    };

    load_chunk(0, 0); cpcommit();
    load_chunk(1, 1); cpcommit();

    for (int kt = 0; kt < NKT; kt++) {
        const int st = kt % 3;
        if (kt == NKT - 1) cpwait<0>(); else cpwait<1>();
        __syncthreads();

        char* sAh = tile(st, 0);
        char* sWh = tile(st, 1);
#pragma unroll
        for (int kc = 0; kc < 4; kc++) {
            const uint32_t acol = (uint32_t)(kc * 32 + a_csel * 2);
            const uint32_t bcol = (uint32_t)(kc * 32 + b_kcol * 2);
            uint32_t ah[2][4];
#pragma unroll
            for (int i = 0; i < 2; i++) {
                uint32_t off = sw128((uint32_t)((wm + i * 16 + a_row) * 128) + acol);
                ldsm_x4(ah[i][0], ah[i][1], ah[i][2], ah[i][3], smaddr(sAh + off));
            }
            uint32_t bh[8][2];
#pragma unroll
            for (int jp = 0; jp < 4; jp++) {
                uint32_t off = sw128((uint32_t)((wn + jp * 16 + b_nrow) * 128) + bcol);
                ldsm_x4(bh[2 * jp][0], bh[2 * jp][1], bh[2 * jp + 1][0], bh[2 * jp + 1][1],
                        smaddr(sWh + off));
            }
#pragma unroll
            for (int i = 0; i < 2; i++)
#pragma unroll
                for (int j = 0; j < 8; j++)
                    mma_f16(acc[i][j], ah[i], bh[j]);
        }

        if (kt + 2 < NKT) {
            load_chunk((kt + 2) % 3, kt + 2);
            cpcommit();
        }
    }

    const int g = lane >> 2, t = lane & 3;
    if (MODE == 0) {
        // hoist col-derived math out of the row loop
#pragma unroll
        for (int j = 0; j < 8; j++)
#pragma unroll
            for (int eo = 0; eo < 2; eo++) {
                int col   = n0 + wn + j * 8 + 2 * t + eo;
                float bv  = bias[col];
                int hh    = col / 192;
                int rem   = col - hh * 192;
                int d     = rem / 3;
                int which = rem - d * 3;
#pragma unroll
                for (int i = 0; i < 2; i++)
#pragma unroll
                    for (int rh = 0; rh < 2; rh++) {
                        int row = m0 + wm + i * 16 + g + rh * 8;
                        float val = acc[i][j][rh * 2 + eo] + bv;
                        int bb = row >> 11;
                        int nn = row & (NSEQ - 1);
                        size_t idx = ((size_t)(bb * NH + hh) * NSEQ + nn) * HD + d;
                        if (which == 0)      g_qh[idx] = __float2half_rn(val * 0.125f);
                        else if (which == 1) g_kh[idx] = __float2half_rn(val);
                        else                 g_vh[idx] = __float2half_rn(val);
                    }
            }
    } else {
#pragma unroll
        for (int i = 0; i < 2; i++)
#pragma unroll
            for (int j = 0; j < 8; j++)
#pragma unroll
                for (int e = 0; e < 4; e++) {
                    int row = m0 + wm + i * 16 + g + (e >> 1) * 8;
                    int col = n0 + wn + j * 8 + 2 * t + (e & 1);
                    Cout[(size_t)row * EMB + col] = acc[i][j][e] + bias[col];
                }
    }
}

// ---------------- flash attention (fp16 1-pass, split-N halves, 2 CTAs/SM) ---
// Block = 128 q-rows of one (b,h), 8 warps. Double-buffered {Kh, Vh}.
// Each KV tile processed in two 64-col halves (online softmax across halves)
// to cut live registers and allow 2 CTAs/SM.
#define AT_TILE (128 * 72)
#define ATTN_SMEM ((1 + 4) * AT_TILE * 2)   // 92160 bytes

__global__ void __launch_bounds__(256, 2) attn_f16()
{
    extern __shared__ f16 sm[];
    f16* Qh = sm;
    auto buf = [&](int st, int arr) -> f16* { return sm + (1 + st * 2 + arr) * AT_TILE; };

    const int tid  = threadIdx.x;
    const int lane = tid & 31;
    const int warp = tid >> 5;
    const int bh = blockIdx.y;
    const int b  = bh >> 4;
    const int h  = bh & 15;
    const int q0 = blockIdx.x * 128;

    const f16* Qgh = g_qh + (size_t)bh * NSEQ * HD;
    const f16* Kgh = g_kh + (size_t)bh * NSEQ * HD;
    const f16* Vgh = g_vh + (size_t)bh * NSEQ * HD;

    const int a_row = lane & 15;
    const int a_csel = (lane >> 4) * 8;
    const int b_nrow = (lane & 7) + (lane >> 4) * 8;
    const int b_kcol = ((lane >> 3) & 1) * 8;
    const int g = lane >> 2, t = lane & 3;

    auto load_kv = [&](int st, int t0) {
#pragma unroll
        for (int i = 0; i < 4; i++) {
            int s = tid + i * 256;
            int r = s >> 3;
            int c = (s & 7) * 8;
            cp16(buf(st, 0) + r * 72 + c, Kgh + (size_t)(t0 + r) * HD + c);
            cp16(buf(st, 1) + r * 72 + c, Vgh + (size_t)(t0 + r) * HD + c);
        }
    };

#pragma unroll
    for (int i = 0; i < 4; i++) {
        int s = tid + i * 256;
        int r = s >> 3;
        int c = (s & 7) * 8;
        cp16(Qh + r * 72 + c, Qgh + (size_t)(q0 + r) * HD + c);
    }
    load_kv(0, 0);
    cpcommit();
    cpwait<0>();
    __syncthreads();

    uint32_t qh[4][4];
#pragma unroll
    for (int kc = 0; kc < 4; kc++) {
        uint32_t ad = smaddr(&Qh[(16 * warp + a_row) * 72 + kc * 16 + a_csel]);
        ldsm_x4(qh[kc][0], qh[kc][1], qh[kc][2], qh[kc][3], ad);
    }

    float oacc[8][4];
#pragma unroll
    for (int j = 0; j < 8; j++)
#pragma unroll
        for (int e = 0; e < 4; e++) oacc[j][e] = 0.f;
    float m0r = -1e30f, m1r = -1e30f, l0 = 0.f, l1 = 0.f;

    for (int ti = 0; ti < NSEQ / 128; ti++) {
        int cb = ti & 1;
        if (ti + 1 < NSEQ / 128) {
            load_kv(cb ^ 1, (ti + 1) * 128);
            cpcommit();
            cpwait<1>();
        } else {
            cpwait<0>();
        }
        __syncthreads();

        f16* Kh = buf(cb, 0);
        f16* Vh = buf(cb, 1);

#pragma unroll
        for (int half = 0; half < 2; half++) {
            // ---- S_half = Qh Kh^T (64 cols) ----
            float sacc[8][4];
#pragma unroll
            for (int j = 0; j < 8; j++)
#pragma unroll
                for (int e = 0; e < 4; e++) sacc[j][e] = 0.f;

#pragma unroll
            for (int kc = 0; kc < 4; kc++) {
#pragma unroll
                for (int jp = 0; jp < 4; jp++) {
                    uint32_t bh4[4];
                    uint32_t ad = smaddr(&Kh[((half * 4 + jp) * 16 + b_nrow) * 72
                                             + kc * 16 + b_kcol]);
                    ldsm_x4(bh4[0], bh4[1], bh4[2], bh4[3], ad);
                    mma_f16(sacc[2 * jp],     qh[kc], &bh4[0]);
                    mma_f16(sacc[2 * jp + 1], qh[kc], &bh4[2]);
                }
            }

            // ---- online softmax over this half ----
            float mx0 = -1e30f, mx1 = -1e30f;
#pragma unroll
            for (int j = 0; j < 8; j++) {
                mx0 = fmaxf(mx0, fmaxf(sacc[j][0], sacc[j][1]));
                mx1 = fmaxf(mx1, fmaxf(sacc[j][2], sacc[j][3]));
            }
            mx0 = fmaxf(mx0, __shfl_xor_sync(0xffffffffu, mx0, 1));
            mx0 = fmaxf(mx0, __shfl_xor_sync(0xffffffffu, mx0, 2));
            mx1 = fmaxf(mx1, __shfl_xor_sync(0xffffffffu, mx1, 1));
            mx1 = fmaxf(mx1, __shfl_xor_sync(0xffffffffu, mx1, 2));
            float mn0 = fmaxf(m0r, mx0), mn1 = fmaxf(m1r, mx1);
            float al0 = fast_exp(m0r - mn0), al1 = fast_exp(m1r - mn1);
            m0r = mn0; m1r = mn1;

            float s0 = 0.f, s1 = 0.f;
            uint32_t aph[4][4];
#pragma unroll
            for (int j2 = 0; j2 < 4; j2++) {
                float p[8];
                p[0] = fast_exp(sacc[2 * j2][0] - mn0);
                p[1] = fast_exp(sacc[2 * j2][1] - mn0);
                p[2] = fast_exp(sacc[2 * j2][2] - mn1);
                p[3] = fast_exp(sacc[2 * j2][3] - mn1);
                p[4] = fast_exp(sacc[2 * j2 + 1][0] - mn0);
                p[5] = fast_exp(sacc[2 * j2 + 1][1] - mn0);
                p[6] = fast_exp(sacc[2 * j2 + 1][2] - mn1);
                p[7] = fast_exp(sacc[2 * j2 + 1][3] - mn1);
                s0 += p[0] + p[1] + p[4] + p[5];
                s1 += p[2] + p[3] + p[6] + p[7];
                aph[j2][0] = pack2f(p[0], p[1]);
                aph[j2][1] = pack2f(p[2], p[3]);
                aph[j2][2] = pack2f(p[4], p[5]);
                aph[j2][3] = pack2f(p[6], p[7]);
            }
            s0 += __shfl_xor_sync(0xffffffffu, s0, 1);
            s0 += __shfl_xor_sync(0xffffffffu, s0, 2);
            s1 += __shfl_xor_sync(0xffffffffu, s1, 1);
            s1 += __shfl_xor_sync(0xffffffffu, s1, 2);
            l0 = l0 * al0 + s0;
            l1 = l1 * al1 + s1;

#pragma unroll
            for (int j = 0; j < 8; j++) {
                oacc[j][0] *= al0; oacc[j][1] *= al0;
                oacc[j][2] *= al1; oacc[j][3] *= al1;
            }

            // ---- O += P_half V_half (V rows half*64 .. +64) ----
#pragma unroll
            for (int kc = 0; kc < 4; kc++) {
#pragma unroll
                for (int jp = 0; jp < 4; jp++) {
                    uint32_t bh4[4];
                    uint32_t ad = smaddr(&Vh[(half * 64 + kc * 16 + a_row) * 72
                                             + jp * 16 + a_csel]);
                    ldsm_x4t(bh4[0], bh4[1], bh4[2], bh4[3], ad);
                    mma_f16(oacc[2 * jp],     aph[kc], &bh4[0]);
                    mma_f16(oacc[2 * jp + 1], aph[kc], &bh4[2]);
                }
            }
        }
        __syncthreads();
    }

    // ---- epilogue: round(O/l) -> g_atth at [b, q, h*64+d] ----
    float inv0 = 1.0f / l0;
    float inv1 = 1.0f / l1;
#pragma unroll
    for (int j = 0; j < 8; j++)
#pragma unroll
        for (int e = 0; e < 4; e++) {
            int row = 16 * warp + g + (e >> 1) * 8;
            int col = j * 8 + 2 * t + (e & 1);
            float val = oacc[j][e] * ((e >> 1) ? inv1 : inv0);
            size_t off = ((size_t)b * NSEQ + q0 + row) * EMB + h * HD + col;
            g_atth[off] = __float2half_rn(val);
        }
}

// ---------------------------------------------------------------------------
extern "C" void kernel_launch(void* const* d_in, const int* in_sizes, int n_in,
                              void* d_out, int out_size)
{
    const float* x      = (const float*)d_in[0];
    const float* w_qkv  = (const float*)d_in[1];
    const float* b_qkv  = (const float*)d_in[2];
    const float* w_proj = (const float*)d_in[3];
    const float* b_proj = (const float*)d_in[4];
    float* out = (float*)d_out;

    cudaFuncSetAttribute((const void*)gemm_f16<0>,
                         cudaFuncAttributeMaxDynamicSharedMemorySize, GEMM_SMEM);
    cudaFuncSetAttribute((const void*)gemm_f16<1>,
                         cudaFuncAttributeMaxDynamicSharedMemorySize, GEMM_SMEM);
    cudaFuncSetAttribute(attn_f16, cudaFuncAttributeMaxDynamicSharedMemorySize, (int)ATTN_SMEM);

    f16 *xh, *wqh, *wph, *atth;
    cudaGetSymbolAddress((void**)&xh,  g_xh);
    cudaGetSymbolAddress((void**)&wqh, g_wqh);
    cudaGetSymbolAddress((void**)&wph, g_wph);
    cudaGetSymbolAddress((void**)&atth, g_atth);

    // 1) round inputs to fp16
    round1_kernel<<<(NTOK * EMB) / 1024, 256>>>((const float4*)x,
        (__half2*)xh, NTOK * EMB / 4);
    round1_kernel<<<(QKVN * EMB) / 1024, 256>>>((const float4*)w_qkv,
        (__half2*)wqh, QKVN * EMB / 4);
    round1_kernel<<<(EMB * EMB) / 1024, 256>>>((const float4*)w_proj,
        (__half2*)wph, EMB * EMB / 4);

    // 2) QKV projection + scatter (q pre-scaled by 1/8)
    gemm_f16<0><<<dim3(QKVN / 128, NTOK / 128), 256, GEMM_SMEM>>>(
        xh, wqh, b_qkv, nullptr);

    // 3) flash attention
    attn_f16<<<dim3(NSEQ / 128, BB * NH), 256, ATTN_SMEM>>>();

    // 4) output projection
    gemm_f16<1><<<dim3(EMB / 128, NTOK / 128), 256, GEMM_SMEM>>>(
        atth, wph, b_proj, out);
}